// round 8
// baseline (speedup 1.0000x reference)
#include <cuda_runtime.h>
#include <math.h>

#define Bq   32
#define Lq   512
#define Hq   512
#define DIN  832
#define G3   1536
#define BL   (Bq*Lq)          // 16384

// ------------------------- scratch (device globals) -------------------------
__device__ __align__(16) float g_X[2][(size_t)BL * DIN];      // 109 MB
__device__ __align__(16) float g_gi[4][(size_t)BL * G3];      // 402 MB
__device__ __align__(16) float g_h[4][2][Bq * Hq];            // ping-pong hidden [b][k]
__device__ __align__(16) float g_enc[2][(size_t)BL * 1024];   // 134 MB
__device__ __align__(16) float g_sim[(size_t)Bq * Lq * Lq];   // 33.5 MB
__device__ __align__(16) float g_rn[2][BL];                   // 1/row-norm of enc
__device__ __align__(16) float g_max1[BL], g_rel1[BL], g_max2[BL], g_rel2[BL];
__device__ __align__(16) float g_feat[Bq * 768];
__device__ int g_flag[4][32];
__device__ unsigned g_ctr[4];

__device__ __forceinline__ unsigned f2tf(float x) {
    unsigned y;
    asm("cvt.rna.tf32.f32 %0, %1;" : "=r"(y) : "f"(x));
    return y;
}

__device__ __forceinline__ void cpa16(void* dst, const void* src) {
    unsigned d = (unsigned)__cvta_generic_to_shared(dst);
    asm volatile("cp.async.cg.shared.global [%0], [%1], 16;\n" :: "r"(d), "l"(src));
}

// ------------------------- init (reset recurrence state) -------------------------
__global__ void k_init() {
    int i = blockIdx.x * blockDim.x + threadIdx.x;
    if (i < 4 * 2 * Hq * Bq) (&g_h[0][0][0])[i] = 0.f;
    if (i < 4) g_ctr[i] = 0u;
    if (i < 128) (&g_flag[0][0])[i] = 0;
}

// ------------------------- embedding concat -------------------------
__global__ void k_embed(const int* __restrict__ w1, const int* __restrict__ w2,
                        const int* __restrict__ p1, const int* __restrict__ p2,
                        const int* __restrict__ tb1, const int* __restrict__ te1,
                        const int* __restrict__ tb2, const int* __restrict__ te2,
                        const float* __restrict__ ew, const float* __restrict__ ep,
                        const float* __restrict__ pe) {
    int tok  = blockIdx.x;
    int side = blockIdx.y;
    int t    = tok & (Lq - 1);
    const int* w  = side ? w2  : w1;
    const int* pp = side ? p2  : p1;
    const int* tb = side ? tb2 : tb1;
    const int* te = side ? te2 : te1;
    int wi = w[tok], pi = pp[tok], bi = tb[tok], ei = te[tok];
    float* dst = g_X[side] + (size_t)tok * DIN;
    const float* s0 = ew + (size_t)wi * 256;
    const float* s1 = ep + (size_t)pi * 256;
    for (int i = threadIdx.x; i < 256; i += 128) {
        dst[i]       = s0[i];
        dst[256 + i] = s1[i];
    }
    const float* q0 = pe + t * 64;
    const float* q1 = pe + bi * 64;
    const float* q2 = pe + ei * 64;
    const float* q3 = pe + (ei - t) * 64;
    const float* q4 = pe + (t - bi) * 64;
    for (int i = threadIdx.x; i < 64; i += 128) {
        dst[512 + i] = q0[i];
        dst[576 + i] = q1[i];
        dst[640 + i] = q2[i];
        dst[704 + i] = q3[i];
        dst[768 + i] = q4[i];
    }
}

// ------------------------- unified tf32 tensor GEMM (cp.async 3-stage) -------------------------
// mode 0: gi (z=side*2+dir, reversed A gather for dir=1, +bias).
// mode 1: sim (z=batch, A=enc1[z], B=enc2[z], epilogue scales by rn1[m]*rn2[n]).
#define TSTR 36
#define NSTG 3
#define MMT_SLOT (2 * 128 * TSTR)
#define MMT_SMEM (NSTG * MMT_SLOT * 4)

__global__ void __launch_bounds__(256, 2) k_mmt(
    int mode, const float* __restrict__ wih, const float* __restrict__ bih,
    const int* __restrict__ len1, const int* __restrict__ len2)
{
    extern __shared__ float smd[];
    const float *A, *B, *bias = 0;
    float* C;
    int K, N, rev = 0;
    const int* lens = 0;
    int z = blockIdx.z;
    int m0 = blockIdx.y * 128, n0 = blockIdx.x * 128;
    if (mode == 0) {
        int side = z >> 1, dir = z & 1;
        A = g_X[side];
        B = wih + (size_t)dir * G3 * DIN;
        bias = bih + dir * G3;
        C = g_gi[z];
        K = DIN; N = G3;
        lens = side ? len2 : len1;
        rev = dir;
    } else {
        A = g_enc[0] + (size_t)z * Lq * 1024;
        B = g_enc[1] + (size_t)z * Lq * 1024;
        C = g_sim + (size_t)z * Lq * Lq;
        K = 1024; N = Lq;
    }
    int tid = threadIdx.x;

    const float* asrc[4]; const float* bsrc[4]; int cdst[4];
#pragma unroll
    for (int i = 0; i < 4; i++) {
        int c = tid + 256 * i;
        int row = c >> 3, q = c & 7;
        int ar = m0 + row;
        if (rev) {
            int b = ar >> 9, t = ar & 511;
            int Lb = lens[b];
            ar = (b << 9) + ((t < Lb) ? (Lb - 1 - t) : t);
        }
        asrc[i] = A + (size_t)ar * K + q * 4;
        bsrc[i] = B + (size_t)(n0 + row) * K + q * 4;
        cdst[i] = row * TSTR + q * 4;
    }

    int KT = K / 32;
#pragma unroll
    for (int s = 0; s < 2; s++) {
        float* As = smd + s * MMT_SLOT;
        float* Bs = As + 128 * TSTR;
#pragma unroll
        for (int i = 0; i < 4; i++) {
            cpa16(As + cdst[i], asrc[i] + s * 32);
            cpa16(Bs + cdst[i], bsrc[i] + s * 32);
        }
        asm volatile("cp.async.commit_group;\n");
    }

    int lane = tid & 31, warp = tid >> 5;
    int mbase = (warp & 3) * 32, nbase = (warp >> 2) * 64;

    float c[2][8][4];
#pragma unroll
    for (int i = 0; i < 2; i++)
#pragma unroll
        for (int j = 0; j < 8; j++)
#pragma unroll
            for (int r = 0; r < 4; r++) c[i][j][r] = 0.f;

    for (int kt = 0; kt < KT; kt++) {
        asm volatile("cp.async.wait_group 1;\n");
        __syncthreads();
        int slot = kt % NSTG;
        const unsigned* Au = (const unsigned*)(smd + slot * MMT_SLOT);
        const unsigned* Bu = Au + 128 * TSTR;
        if (kt + 2 < KT) {
            int s2 = (kt + 2) % NSTG;
            float* As2 = smd + s2 * MMT_SLOT;
            float* Bs2 = As2 + 128 * TSTR;
#pragma unroll
            for (int i = 0; i < 4; i++) {
                cpa16(As2 + cdst[i], asrc[i] + (kt + 2) * 32);
                cpa16(Bs2 + cdst[i], bsrc[i] + (kt + 2) * 32);
            }
        }
        asm volatile("cp.async.commit_group;\n");

#pragma unroll
        for (int kk = 0; kk < 32; kk += 8) {
            unsigned a[2][4];
#pragma unroll
            for (int i = 0; i < 2; i++) {
                int ao = (mbase + i * 16 + (lane >> 2)) * TSTR + kk + (lane & 3);
                a[i][0] = Au[ao];
                a[i][1] = Au[ao + 8 * TSTR];
                a[i][2] = Au[ao + 4];
                a[i][3] = Au[ao + 8 * TSTR + 4];
            }
#pragma unroll
            for (int j = 0; j < 8; j++) {
                int bo = (nbase + j * 8 + (lane >> 2)) * TSTR + kk + (lane & 3);
                unsigned b0 = Bu[bo], b1 = Bu[bo + 4];
#pragma unroll
                for (int i = 0; i < 2; i++) {
                    asm volatile(
                        "mma.sync.aligned.m16n8k8.row.col.f32.tf32.tf32.f32 "
                        "{%0,%1,%2,%3}, {%4,%5,%6,%7}, {%8,%9}, {%0,%1,%2,%3};"
                        : "+f"(c[i][j][0]), "+f"(c[i][j][1]),
                          "+f"(c[i][j][2]), "+f"(c[i][j][3])
                        : "r"(a[i][0]), "r"(a[i][1]), "r"(a[i][2]), "r"(a[i][3]),
                          "r"(b0), "r"(b1));
                }
            }
        }
    }

    int crow = lane >> 2, ccol = (lane & 3) * 2;
    const float* rn1 = g_rn[0] + z * Lq;
    const float* rn2 = g_rn[1] + z * Lq;
#pragma unroll
    for (int i = 0; i < 2; i++) {
#pragma unroll
        for (int j = 0; j < 8; j++) {
            int m = m0 + mbase + i * 16 + crow;
            int n = n0 + nbase + j * 8 + ccol;
            float v00 = c[i][j][0], v01 = c[i][j][1];
            float v10 = c[i][j][2], v11 = c[i][j][3];
            if (mode == 0) {
                float b0v = bias[n], b1v = bias[n + 1];
                v00 += b0v; v01 += b1v; v10 += b0v; v11 += b1v;
            } else {
                float sm0 = rn1[m], sm1 = rn1[m + 8];
                float sn0 = rn2[n], sn1 = rn2[n + 1];
                v00 *= sm0 * sn0; v01 *= sm0 * sn1;
                v10 *= sm1 * sn0; v11 *= sm1 * sn1;
            }
            C[(size_t)m * N + n]           = v00;
            C[(size_t)m * N + n + 1]       = v01;
            C[(size_t)(m + 8) * N + n]     = v10;
            C[(size_t)(m + 8) * N + n + 1] = v11;
        }
    }
}

// ------------------------- persistent GRU scan (flag-synced tensor recurrence) -------------------------
#define WSTR 516
#define GRU_SMEM ((48 * WSTR + 32 * WSTR + 8 * 48 * 33) * 4)

__global__ void __launch_bounds__(256, 1) k_gru(
    const float* __restrict__ whh, const float* __restrict__ bhh,
    const int* __restrict__ len1, const int* __restrict__ len2)
{
    extern __shared__ unsigned smu[];
    unsigned* Ws  = smu;                                 // [48][WSTR] tf32 bits
    float*    hT  = (float*)(smu + 48 * WSTR);           // [32][WSTR]
    float*    part = hT + 32 * WSTR;                     // [8][48*33]
    const unsigned* hTu = (const unsigned*)hT;

    int chain = blockIdx.x >> 5;
    int blk   = blockIdx.x & 31;
    int side  = chain >> 1, dir = chain & 1;
    int j0    = blk * 16;
    int tid   = threadIdx.x;
    int lane  = tid & 31, warp = tid >> 5;
    const int* lens = side ? len2 : len1;
    const float* gi = g_gi[chain];
    float* enc = g_enc[side];

    for (int i = tid; i < 48 * 512; i += 256) {
        int rr = i >> 9, k = i & 511;
        int g = rr >> 4, u = rr & 15;
        Ws[rr * WSTR + k] = f2tf(whh[((size_t)dir * G3 + g * 512 + j0 + u) * 512 + k]);
    }
    __syncthreads();

    int gb  = tid & 31;
    int u0  = tid >> 5;
    int u1  = u0 + 8;
    int lenb = lens[gb];
    float bhr0 = bhh[dir * G3 +        j0 + u0];
    float bhz0 = bhh[dir * G3 +  512 + j0 + u0];
    float bhn0 = bhh[dir * G3 + 1024 + j0 + u0];
    float bhr1 = bhh[dir * G3 +        j0 + u1];
    float bhz1 = bhh[dir * G3 +  512 + j0 + u1];
    float bhn1 = bhh[dir * G3 + 1024 + j0 + u1];

    // staging geometry: warp w owns k-range [64w, 64w+64), sourced from blocks 4w..4w+3
    const int* myflag = &g_flag[chain][4 * warp + (lane & 3)];
    int halfb = lane >> 4;
    int kof   = (warp << 6) + (lane & 15) * 4;

    for (int t = 0; t < Lq; ++t) {
        int p = t & 1;

        // gi prefetch (independent of h availability)
        size_t tok = (size_t)((gb << 9) | t);
        const float* gp = gi + tok * G3 + j0;
        float ir0 = __ldg(gp + u0), iz0 = __ldg(gp + 512 + u0), in0 = __ldg(gp + 1024 + u0);
        float ir1 = __ldg(gp + u1), iz1 = __ldg(gp + 512 + u1), in1 = __ldg(gp + 1024 + u1);

        // wait for this warp's 4 source blocks to publish h(t)
        if (lane < 4) {
            int v;
            do {
                asm volatile("ld.acquire.gpu.global.b32 %0, [%1];" : "=r"(v) : "l"(myflag));
            } while (v < t);
        }
        __syncwarp();

        // stage own k-range: 16 x (coalesced LDG.128 -> STS.128)
        const float* hsrc = g_h[chain][p];
#pragma unroll
        for (int i = 0; i < 16; i++) {
            int b = 2 * i + halfb;
            float4 v = __ldcg((const float4*)(hsrc + b * 512 + kof));
            *(float4*)(hT + b * WSTR + kof) = v;
        }
        __syncwarp();

        // mma: warp's K slice [64w, 64w+64)
        float acc[3][4][4];
#pragma unroll
        for (int mt = 0; mt < 3; mt++)
#pragma unroll
            for (int nt = 0; nt < 4; nt++)
#pragma unroll
                for (int r = 0; r < 4; r++) acc[mt][nt][r] = 0.f;

        int kbase = warp << 6;
#pragma unroll
        for (int ks8 = 0; ks8 < 64; ks8 += 8) {
            int k = kbase + ks8;
            unsigned a[3][4];
#pragma unroll
            for (int mt = 0; mt < 3; mt++) {
                int ao = (mt * 16 + (lane >> 2)) * WSTR + k + (lane & 3);
                a[mt][0] = Ws[ao];
                a[mt][1] = Ws[ao + 8 * WSTR];
                a[mt][2] = Ws[ao + 4];
                a[mt][3] = Ws[ao + 8 * WSTR + 4];
            }
            unsigned bfr[4][2];
#pragma unroll
            for (int nt = 0; nt < 4; nt++) {
                int bo = (nt * 8 + (lane >> 2)) * WSTR + k + (lane & 3);
                bfr[nt][0] = hTu[bo];
                bfr[nt][1] = hTu[bo + 4];
            }
#pragma unroll
            for (int mt = 0; mt < 3; mt++)
#pragma unroll
                for (int nt = 0; nt < 4; nt++) {
                    asm volatile(
                        "mma.sync.aligned.m16n8k8.row.col.f32.tf32.tf32.f32 "
                        "{%0,%1,%2,%3}, {%4,%5,%6,%7}, {%8,%9}, {%0,%1,%2,%3};"
                        : "+f"(acc[mt][nt][0]), "+f"(acc[mt][nt][1]),
                          "+f"(acc[mt][nt][2]), "+f"(acc[mt][nt][3])
                        : "r"(a[mt][0]), "r"(a[mt][1]), "r"(a[mt][2]), "r"(a[mt][3]),
                          "r"(bfr[nt][0]), "r"(bfr[nt][1]));
                }
        }
        {
            float* pw = part + warp * (48 * 33);
            int crow = lane >> 2, ccol = 2 * (lane & 3);
#pragma unroll
            for (int mt = 0; mt < 3; mt++)
#pragma unroll
                for (int nt = 0; nt < 4; nt++) {
                    int r0 = mt * 16 + crow;
                    int c0 = nt * 8 + ccol;
                    pw[r0 * 33 + c0]           = acc[mt][nt][0];
                    pw[r0 * 33 + c0 + 1]       = acc[mt][nt][1];
                    pw[(r0 + 8) * 33 + c0]     = acc[mt][nt][2];
                    pw[(r0 + 8) * 33 + c0 + 1] = acc[mt][nt][3];
                }
        }
        __syncthreads();

        for (int i = tid; i < 1536; i += 256) {
            int rr = i >> 5, b = i & 31;
            float s = 0.f;
#pragma unroll
            for (int w = 0; w < 8; w++) s += part[w * (48 * 33) + rr * 33 + b];
            part[rr * 33 + b] = s;
        }
        __syncthreads();

        // gates + state update (2 units per thread)
        bool valid = t < lenb;
        int tout = dir ? (valid ? lenb - 1 - t : t) : t;
        size_t otok = (size_t)((gb << 9) | tout);
        float* hdst = g_h[chain][p ^ 1];

        {
            float hr = part[u0 * 33 + gb] + bhr0;
            float hz = part[(16 + u0) * 33 + gb] + bhz0;
            float hn = part[(32 + u0) * 33 + gb] + bhn0;
            float r  = 1.f / (1.f + expf(-(ir0 + hr)));
            float zz = 1.f / (1.f + expf(-(iz0 + hz)));
            float nn = tanhf(in0 + r * hn);
            float hprev = hT[gb * WSTR + j0 + u0];
            float hnew  = (1.f - zz) * nn + zz * hprev;
            hdst[gb * 512 + j0 + u0] = valid ? __uint_as_float(f2tf(hnew)) : hprev;
            enc[otok * 1024 + (dir << 9) + j0 + u0] = valid ? hnew : 0.f;
        }
        {
            float hr = part[u1 * 33 + gb] + bhr1;
            float hz = part[(16 + u1) * 33 + gb] + bhz1;
            float hn = part[(32 + u1) * 33 + gb] + bhn1;
            float r  = 1.f / (1.f + expf(-(ir1 + hr)));
            float zz = 1.f / (1.f + expf(-(iz1 + hz)));
            float nn = tanhf(in1 + r * hn);
            float hprev = hT[gb * WSTR + j0 + u1];
            float hnew  = (1.f - zz) * nn + zz * hprev;
            hdst[gb * 512 + j0 + u1] = valid ? __uint_as_float(f2tf(hnew)) : hprev;
            enc[otok * 1024 + (dir << 9) + j0 + u1] = valid ? hnew : 0.f;
        }

        // publish h(t+1): fence by all writers, then release-store our step flag
        __threadfence();
        __syncthreads();
        if (tid == 0) {
            asm volatile("st.release.gpu.global.b32 [%0], %1;"
                         :: "l"(&g_flag[chain][blk]), "r"(t + 1));
        }
    }
}

// ------------------------- row inverse-norms of enc -------------------------
__global__ void k_norm() {
    const float* row = g_enc[blockIdx.y] + (size_t)blockIdx.x * 1024;
    int tid = threadIdx.x;
    float ss = 0.f;
    for (int i = tid; i < 1024; i += 128) { float v = row[i]; ss += v * v; }
    __shared__ float red[4];
    for (int o = 16; o; o >>= 1) ss += __shfl_down_sync(0xffffffffu, ss, o);
    if ((tid & 31) == 0) red[tid >> 5] = ss;
    __syncthreads();
    if (tid == 0) {
        float tot = red[0] + red[1] + red[2] + red[3];
        g_rn[blockIdx.y][blockIdx.x] = tot > 0.f ? rsqrtf(tot) : 0.f;
    }
}

// ------------------------- row / col max+argmax (first-index ties) -------------------------
__global__ void k_rowmax() {
    int row = blockIdx.x * 8 + (threadIdx.x >> 5);
    int l = threadIdx.x & 31;
    const float* s = g_sim + (size_t)row * Lq;
    float bv = -1e30f; int bi = 0;
    for (int j = l; j < Lq; j += 32) {
        float v = s[j];
        if (v > bv) { bv = v; bi = j; }
    }
    for (int o = 16; o; o >>= 1) {
        float ov = __shfl_down_sync(0xffffffffu, bv, o);
        int   oi = __shfl_down_sync(0xffffffffu, bi, o);
        if (ov > bv || (ov == bv && oi < bi)) { bv = ov; bi = oi; }
    }
    if (l == 0) {
        int i = row & 511;
        g_max1[row] = bv;
        g_rel1[row] = (float)(i - bi);
    }
}

__global__ void k_colmax() {
    int id = blockIdx.x * blockDim.x + threadIdx.x;
    int b = id >> 9, j = id & 511;
    const float* s = g_sim + ((size_t)b * Lq) * Lq + j;
    float bv = -1e30f; int bi = 0;
    for (int i = 0; i < Lq; ++i) {
        float v = s[(size_t)i * Lq];
        if (v > bv) { bv = v; bi = i; }
    }
    g_max2[id] = bv;
    g_rel2[id] = (float)(j - bi);
}

// ------------------------- conv branches + maxpool -------------------------
__global__ void k_head(const float* __restrict__ w2p, const float* __restrict__ w3p,
                       const float* __restrict__ w4p, const float* __restrict__ cb,
                       const float* __restrict__ bg, const float* __restrict__ bb,
                       const float* __restrict__ bm, const float* __restrict__ bvv)
{
    int b = blockIdx.x, br = blockIdx.y;
    __shared__ float x0[512], x1[512];
    const float* ms = br ? g_max2 : g_max1;
    const float* rl = br ? g_rel2 : g_rel1;
    for (int i = threadIdx.x; i < 512; i += 128) {
        x0[i] = ms[b * 512 + i];
        x1[i] = rl[b * 512 + i];
    }
    __syncthreads();
    int c = threadIdx.x;
    float* fout = g_feat + b * 768 + br * 384;
    const float* wp[3] = { w2p, w3p, w4p };
    const int kss[3] = { 2, 3, 4 };
    for (int ki = 0; ki < 3; ++ki) {
        int ks = kss[ki];
        float w0[4], w1[4];
        for (int kk = 0; kk < 4; kk++) {
            w0[kk] = kk < ks ? wp[ki][(c * 2 + 0) * ks + kk] : 0.f;
            w1[kk] = kk < ks ? wp[ki][(c * 2 + 1) * ks + kk] : 0.f;
        }
        float s  = bg[ki * 128 + c] / sqrtf(bvv[ki * 128 + c] + 1e-5f);
        float sh = bb[ki * 128 + c] - bm[ki * 128 + c] * s;
        float bias = cb[ki * 128 + c];
        float best = 0.f;
        for (int p = 0; p <= 512 - ks; ++p) {
            float acc = bias;
#pragma unroll
            for (int kk = 0; kk < 4; kk++)
                if (kk < ks) acc += w0[kk] * x0[p + kk] + w1[kk] * x1[p + kk];
            float y = fmaxf(acc * s + sh, 0.f);
            best = fmaxf(best, y);
        }
        fout[ki * 128 + c] = best;
    }
}

// ------------------------- FC + softmax -------------------------
__global__ void k_fc(const float* __restrict__ fcw, const float* __restrict__ fcb,
                     float* __restrict__ out)
{
    int id = threadIdx.x;
    int b = id >> 1, cls = id & 1;
    float acc = fcb[cls];
    const float* f = g_feat + b * 768;
    const float* wrow = fcw + cls * 768;
    for (int k = 0; k < 768; ++k) acc += f[k] * wrow[k];
    float other = __shfl_xor_sync(0xffffffffu, acc, 1);
    float m = fmaxf(acc, other);
    float e = expf(acc - m);
    float ssum = e + expf(other - m);
    out[id] = e / ssum;
}

// ------------------------- launch -------------------------
extern "C" void kernel_launch(void* const* d_in, const int* in_sizes, int n_in,
                              void* d_out, int out_size)
{
    const int* w1  = (const int*)d_in[0];
    const int* w2  = (const int*)d_in[1];
    const int* p1  = (const int*)d_in[2];
    const int* p2  = (const int*)d_in[3];
    const int* ln1 = (const int*)d_in[4];
    const int* ln2 = (const int*)d_in[5];
    const int* tb1 = (const int*)d_in[6];
    const int* te1 = (const int*)d_in[7];
    const int* tb2 = (const int*)d_in[8];
    const int* te2 = (const int*)d_in[9];
    const float* ew   = (const float*)d_in[10];
    const float* ep   = (const float*)d_in[11];
    const float* pe   = (const float*)d_in[12];
    const float* wih  = (const float*)d_in[13];
    const float* whh  = (const float*)d_in[14];
    const float* bih  = (const float*)d_in[15];
    const float* bhh  = (const float*)d_in[16];
    const float* cw0  = (const float*)d_in[17];
    const float* cw1  = (const float*)d_in[18];
    const float* cw2  = (const float*)d_in[19];
    const float* cb   = (const float*)d_in[20];
    const float* bg   = (const float*)d_in[21];
    const float* bb   = (const float*)d_in[22];
    const float* bm   = (const float*)d_in[23];
    const float* bv   = (const float*)d_in[24];
    const float* fcw  = (const float*)d_in[25];
    const float* fcb  = (const float*)d_in[26];
    float* out = (float*)d_out;

    cudaFuncSetAttribute(k_mmt, cudaFuncAttributeMaxDynamicSharedMemorySize, MMT_SMEM);
    cudaFuncSetAttribute(k_gru, cudaFuncAttributeMaxDynamicSharedMemorySize, GRU_SMEM);

    k_init<<<512, 256>>>();
    k_embed<<<dim3(BL, 2), 128>>>(w1, w2, p1, p2, tb1, te1, tb2, te2, ew, ep, pe);
    k_mmt<<<dim3(G3 / 128, BL / 128, 4), 256, MMT_SMEM>>>(0, wih, bih, ln1, ln2);
    k_gru<<<128, 256, GRU_SMEM>>>(whh, bhh, ln1, ln2);
    k_norm<<<dim3(BL, 2), 128>>>();
    k_mmt<<<dim3(Lq / 128, Lq / 128, Bq), 256, MMT_SMEM>>>(1, 0, 0, 0, 0);
    k_rowmax<<<BL / 8, 256>>>();
    k_colmax<<<BL / 256, 256>>>();
    k_head<<<dim3(Bq, 2), 128>>>(cw0, cw1, cw2, cb, bg, bb, bm, bv);
    k_fc<<<1, 64>>>(fcw, fcb, out);
}

// round 9
// speedup vs baseline: 1.4036x; 1.4036x over previous
#include <cuda_runtime.h>
#include <math.h>

#define Bq   32
#define Lq   512
#define Hq   512
#define DIN  832
#define G3   1536
#define BL   (Bq*Lq)          // 16384

// ------------------------- scratch (device globals) -------------------------
__device__ __align__(16) float g_X[2][(size_t)BL * DIN];      // 109 MB
__device__ __align__(16) float g_gi[4][(size_t)BL * G3];      // 402 MB
__device__ __align__(16) float g_h[4][2][Bq * Hq];            // ping-pong hidden [b][k]
__device__ __align__(16) float g_enc[2][(size_t)BL * 1024];   // 134 MB
__device__ __align__(16) float g_sim[(size_t)Bq * Lq * Lq];   // 33.5 MB
__device__ __align__(16) float g_rn[2][BL];                   // 1/row-norm of enc
__device__ __align__(16) float g_max1[BL], g_rel1[BL], g_max2[BL], g_rel2[BL];
__device__ __align__(16) float g_feat[Bq * 768];
__device__ unsigned g_ctr[4];

__device__ __forceinline__ unsigned f2tf(float x) {
    unsigned y;
    asm("cvt.rna.tf32.f32 %0, %1;" : "=r"(y) : "f"(x));
    return y;
}

__device__ __forceinline__ void cpa16(void* dst, const void* src) {
    unsigned d = (unsigned)__cvta_generic_to_shared(dst);
    asm volatile("cp.async.cg.shared.global [%0], [%1], 16;\n" :: "r"(d), "l"(src));
}

// ------------------------- init (reset recurrence state) -------------------------
__global__ void k_init() {
    int i = blockIdx.x * blockDim.x + threadIdx.x;
    if (i < 4 * 2 * Hq * Bq) (&g_h[0][0][0])[i] = 0.f;
    if (i < 4) g_ctr[i] = 0u;
}

// ------------------------- embedding concat -------------------------
__global__ void k_embed(const int* __restrict__ w1, const int* __restrict__ w2,
                        const int* __restrict__ p1, const int* __restrict__ p2,
                        const int* __restrict__ tb1, const int* __restrict__ te1,
                        const int* __restrict__ tb2, const int* __restrict__ te2,
                        const float* __restrict__ ew, const float* __restrict__ ep,
                        const float* __restrict__ pe) {
    int tok  = blockIdx.x;
    int side = blockIdx.y;
    int t    = tok & (Lq - 1);
    const int* w  = side ? w2  : w1;
    const int* pp = side ? p2  : p1;
    const int* tb = side ? tb2 : tb1;
    const int* te = side ? te2 : te1;
    int wi = w[tok], pi = pp[tok], bi = tb[tok], ei = te[tok];
    float* dst = g_X[side] + (size_t)tok * DIN;
    const float* s0 = ew + (size_t)wi * 256;
    const float* s1 = ep + (size_t)pi * 256;
    for (int i = threadIdx.x; i < 256; i += 128) {
        dst[i]       = s0[i];
        dst[256 + i] = s1[i];
    }
    const float* q0 = pe + t * 64;
    const float* q1 = pe + bi * 64;
    const float* q2 = pe + ei * 64;
    const float* q3 = pe + (ei - t) * 64;
    const float* q4 = pe + (t - bi) * 64;
    for (int i = threadIdx.x; i < 64; i += 128) {
        dst[512 + i] = q0[i];
        dst[576 + i] = q1[i];
        dst[640 + i] = q2[i];
        dst[704 + i] = q3[i];
        dst[768 + i] = q4[i];
    }
}

// ------------------------- unified tf32 tensor GEMM (cp.async 3-stage) -------------------------
// mode 0: gi (z=side*2+dir, reversed A gather for dir=1, +bias).
// mode 1: sim (z=batch, A=enc1[z], B=enc2[z], epilogue scales by rn1[m]*rn2[n]).
#define TSTR 36
#define NSTG 3
#define MMT_SLOT (2 * 128 * TSTR)
#define MMT_SMEM (NSTG * MMT_SLOT * 4)

__global__ void __launch_bounds__(256, 2) k_mmt(
    int mode, const float* __restrict__ wih, const float* __restrict__ bih,
    const int* __restrict__ len1, const int* __restrict__ len2)
{
    extern __shared__ float smd[];
    const float *A, *B, *bias = 0;
    float* C;
    int K, N, rev = 0;
    const int* lens = 0;
    int z = blockIdx.z;
    int m0 = blockIdx.y * 128, n0 = blockIdx.x * 128;
    if (mode == 0) {
        int side = z >> 1, dir = z & 1;
        A = g_X[side];
        B = wih + (size_t)dir * G3 * DIN;
        bias = bih + dir * G3;
        C = g_gi[z];
        K = DIN; N = G3;
        lens = side ? len2 : len1;
        rev = dir;
    } else {
        A = g_enc[0] + (size_t)z * Lq * 1024;
        B = g_enc[1] + (size_t)z * Lq * 1024;
        C = g_sim + (size_t)z * Lq * Lq;
        K = 1024; N = Lq;
    }
    int tid = threadIdx.x;

    const float* asrc[4]; const float* bsrc[4]; int cdst[4];
#pragma unroll
    for (int i = 0; i < 4; i++) {
        int c = tid + 256 * i;
        int row = c >> 3, q = c & 7;
        int ar = m0 + row;
        if (rev) {
            int b = ar >> 9, t = ar & 511;
            int Lb = lens[b];
            ar = (b << 9) + ((t < Lb) ? (Lb - 1 - t) : t);
        }
        asrc[i] = A + (size_t)ar * K + q * 4;
        bsrc[i] = B + (size_t)(n0 + row) * K + q * 4;
        cdst[i] = row * TSTR + q * 4;
    }

    int KT = K / 32;
#pragma unroll
    for (int s = 0; s < 2; s++) {
        float* As = smd + s * MMT_SLOT;
        float* Bs = As + 128 * TSTR;
#pragma unroll
        for (int i = 0; i < 4; i++) {
            cpa16(As + cdst[i], asrc[i] + s * 32);
            cpa16(Bs + cdst[i], bsrc[i] + s * 32);
        }
        asm volatile("cp.async.commit_group;\n");
    }

    int lane = tid & 31, warp = tid >> 5;
    int mbase = (warp & 3) * 32, nbase = (warp >> 2) * 64;

    float c[2][8][4];
#pragma unroll
    for (int i = 0; i < 2; i++)
#pragma unroll
        for (int j = 0; j < 8; j++)
#pragma unroll
            for (int r = 0; r < 4; r++) c[i][j][r] = 0.f;

    for (int kt = 0; kt < KT; kt++) {
        asm volatile("cp.async.wait_group 1;\n");
        __syncthreads();
        int slot = kt % NSTG;
        const unsigned* Au = (const unsigned*)(smd + slot * MMT_SLOT);
        const unsigned* Bu = Au + 128 * TSTR;
        if (kt + 2 < KT) {
            int s2 = (kt + 2) % NSTG;
            float* As2 = smd + s2 * MMT_SLOT;
            float* Bs2 = As2 + 128 * TSTR;
#pragma unroll
            for (int i = 0; i < 4; i++) {
                cpa16(As2 + cdst[i], asrc[i] + (kt + 2) * 32);
                cpa16(Bs2 + cdst[i], bsrc[i] + (kt + 2) * 32);
            }
        }
        asm volatile("cp.async.commit_group;\n");

#pragma unroll
        for (int kk = 0; kk < 32; kk += 8) {
            unsigned a[2][4];
#pragma unroll
            for (int i = 0; i < 2; i++) {
                int ao = (mbase + i * 16 + (lane >> 2)) * TSTR + kk + (lane & 3);
                a[i][0] = Au[ao];
                a[i][1] = Au[ao + 8 * TSTR];
                a[i][2] = Au[ao + 4];
                a[i][3] = Au[ao + 8 * TSTR + 4];
            }
#pragma unroll
            for (int j = 0; j < 8; j++) {
                int bo = (nbase + j * 8 + (lane >> 2)) * TSTR + kk + (lane & 3);
                unsigned b0 = Bu[bo], b1 = Bu[bo + 4];
#pragma unroll
                for (int i = 0; i < 2; i++) {
                    asm volatile(
                        "mma.sync.aligned.m16n8k8.row.col.f32.tf32.tf32.f32 "
                        "{%0,%1,%2,%3}, {%4,%5,%6,%7}, {%8,%9}, {%0,%1,%2,%3};"
                        : "+f"(c[i][j][0]), "+f"(c[i][j][1]),
                          "+f"(c[i][j][2]), "+f"(c[i][j][3])
                        : "r"(a[i][0]), "r"(a[i][1]), "r"(a[i][2]), "r"(a[i][3]),
                          "r"(b0), "r"(b1));
                }
            }
        }
    }

    int crow = lane >> 2, ccol = (lane & 3) * 2;
    const float* rn1 = g_rn[0] + z * Lq;
    const float* rn2 = g_rn[1] + z * Lq;
#pragma unroll
    for (int i = 0; i < 2; i++) {
#pragma unroll
        for (int j = 0; j < 8; j++) {
            int m = m0 + mbase + i * 16 + crow;
            int n = n0 + nbase + j * 8 + ccol;
            float v00 = c[i][j][0], v01 = c[i][j][1];
            float v10 = c[i][j][2], v11 = c[i][j][3];
            if (mode == 0) {
                float b0v = bias[n], b1v = bias[n + 1];
                v00 += b0v; v01 += b1v; v10 += b0v; v11 += b1v;
            } else {
                float sm0 = rn1[m], sm1 = rn1[m + 8];
                float sn0 = rn2[n], sn1 = rn2[n + 1];
                v00 *= sm0 * sn0; v01 *= sm0 * sn1;
                v10 *= sm1 * sn0; v11 *= sm1 * sn1;
            }
            C[(size_t)m * N + n]           = v00;
            C[(size_t)m * N + n + 1]       = v01;
            C[(size_t)(m + 8) * N + n]     = v10;
            C[(size_t)(m + 8) * N + n + 1] = v11;
        }
    }
}

// ------------------------- persistent GRU scan (tensor recurrence, direct-LDG h) -------------------------
// gh[48,32] = Ws[48,512] @ h[32,512]^T ; B-fragments read straight from L2-resident g_h.
#define WSTR 516
#define GRU_SMEM ((48 * WSTR + 8 * 48 * 33) * 4)

__global__ void __launch_bounds__(256, 1) k_gru(
    const float* __restrict__ whh, const float* __restrict__ bhh,
    const int* __restrict__ len1, const int* __restrict__ len2)
{
    extern __shared__ unsigned smu[];
    unsigned* Ws  = smu;                                 // [48][WSTR] tf32 bits
    float*    part = (float*)(smu + 48 * WSTR);          // [8][48*33]

    int chain = blockIdx.x >> 5;
    int blk   = blockIdx.x & 31;
    int side  = chain >> 1, dir = chain & 1;
    int j0    = blk * 16;
    int tid   = threadIdx.x;
    int lane  = tid & 31, warp = tid >> 5;
    const int* lens = side ? len2 : len1;
    const float* gi = g_gi[chain];
    float* enc = g_enc[side];

    for (int i = tid; i < 48 * 512; i += 256) {
        int rr = i >> 9, k = i & 511;
        int g = rr >> 4, u = rr & 15;
        Ws[rr * WSTR + k] = f2tf(whh[((size_t)dir * G3 + g * 512 + j0 + u) * 512 + k]);
    }
    __syncthreads();

    int gb  = tid & 31;
    int u0  = tid >> 5;
    int u1  = u0 + 8;
    int lenb = lens[gb];
    float bhr0 = bhh[dir * G3 +        j0 + u0];
    float bhz0 = bhh[dir * G3 +  512 + j0 + u0];
    float bhn0 = bhh[dir * G3 + 1024 + j0 + u0];
    float bhr1 = bhh[dir * G3 +        j0 + u1];
    float bhz1 = bhh[dir * G3 +  512 + j0 + u1];
    float bhn1 = bhh[dir * G3 + 1024 + j0 + u1];

    int kbase = warp << 6;                      // warp's K slice [64w, 64w+64)
    unsigned tgt = 0;
    for (int t = 0; t < Lq; ++t) {
        int p = t & 1;
        const float* hsrc = g_h[chain][p];

        // prefetch gi gate values + previous hidden state (hide behind mma)
        size_t tok = (size_t)((gb << 9) | t);
        const float* gp = gi + tok * G3 + j0;
        float ir0 = __ldg(gp + u0), iz0 = __ldg(gp + 512 + u0), in0 = __ldg(gp + 1024 + u0);
        float ir1 = __ldg(gp + u1), iz1 = __ldg(gp + 512 + u1), in1 = __ldg(gp + 1024 + u1);
        float hp0 = __ldcg(hsrc + gb * 512 + j0 + u0);
        float hp1 = __ldcg(hsrc + gb * 512 + j0 + u1);

        // mma with B-fragments loaded directly from global h
        float acc[3][4][4];
#pragma unroll
        for (int mt = 0; mt < 3; mt++)
#pragma unroll
            for (int nt = 0; nt < 4; nt++)
#pragma unroll
                for (int r = 0; r < 4; r++) acc[mt][nt][r] = 0.f;

        const float* hb = hsrc + (lane >> 2) * 512 + (lane & 3);
#pragma unroll
        for (int ks8 = 0; ks8 < 64; ks8 += 8) {
            int k = kbase + ks8;
            unsigned a[3][4];
#pragma unroll
            for (int mt = 0; mt < 3; mt++) {
                int ao = (mt * 16 + (lane >> 2)) * WSTR + k + (lane & 3);
                a[mt][0] = Ws[ao];
                a[mt][1] = Ws[ao + 8 * WSTR];
                a[mt][2] = Ws[ao + 4];
                a[mt][3] = Ws[ao + 8 * WSTR + 4];
            }
            unsigned bfr[4][2];
#pragma unroll
            for (int nt = 0; nt < 4; nt++) {
                const float* hq = hb + nt * 4096 + k;
                bfr[nt][0] = __float_as_uint(__ldcg(hq));
                bfr[nt][1] = __float_as_uint(__ldcg(hq + 4));
            }
#pragma unroll
            for (int mt = 0; mt < 3; mt++)
#pragma unroll
                for (int nt = 0; nt < 4; nt++) {
                    asm volatile(
                        "mma.sync.aligned.m16n8k8.row.col.f32.tf32.tf32.f32 "
                        "{%0,%1,%2,%3}, {%4,%5,%6,%7}, {%8,%9}, {%0,%1,%2,%3};"
                        : "+f"(acc[mt][nt][0]), "+f"(acc[mt][nt][1]),
                          "+f"(acc[mt][nt][2]), "+f"(acc[mt][nt][3])
                        : "r"(a[mt][0]), "r"(a[mt][1]), "r"(a[mt][2]), "r"(a[mt][3]),
                          "r"(bfr[nt][0]), "r"(bfr[nt][1]));
                }
        }
        {
            float* pw = part + warp * (48 * 33);
            int crow = lane >> 2, ccol = 2 * (lane & 3);
#pragma unroll
            for (int mt = 0; mt < 3; mt++)
#pragma unroll
                for (int nt = 0; nt < 4; nt++) {
                    int r0 = mt * 16 + crow;
                    int c0 = nt * 8 + ccol;
                    pw[r0 * 33 + c0]           = acc[mt][nt][0];
                    pw[r0 * 33 + c0 + 1]       = acc[mt][nt][1];
                    pw[(r0 + 8) * 33 + c0]     = acc[mt][nt][2];
                    pw[(r0 + 8) * 33 + c0 + 1] = acc[mt][nt][3];
                }
        }
        __syncthreads();

        for (int i = tid; i < 1536; i += 256) {
            int rr = i >> 5, b = i & 31;
            float s = 0.f;
#pragma unroll
            for (int w = 0; w < 8; w++) s += part[w * (48 * 33) + rr * 33 + b];
            part[rr * 33 + b] = s;
        }
        __syncthreads();

        // gates + h update (2 units per thread); enc store deferred past publish
        bool valid = t < lenb;
        int tout = dir ? (valid ? lenb - 1 - t : t) : t;
        size_t otok = (size_t)((gb << 9) | tout);
        float* hdst = g_h[chain][p ^ 1];

        float e0, e1;
        {
            float hr = part[u0 * 33 + gb] + bhr0;
            float hz = part[(16 + u0) * 33 + gb] + bhz0;
            float hn = part[(32 + u0) * 33 + gb] + bhn0;
            float r  = 1.f / (1.f + expf(-(ir0 + hr)));
            float zz = 1.f / (1.f + expf(-(iz0 + hz)));
            float nn = tanhf(in0 + r * hn);
            float hnew = (1.f - zz) * nn + zz * hp0;
            hdst[gb * 512 + j0 + u0] = valid ? __uint_as_float(f2tf(hnew)) : hp0;
            e0 = valid ? hnew : 0.f;
        }
        {
            float hr = part[u1 * 33 + gb] + bhr1;
            float hz = part[(16 + u1) * 33 + gb] + bhz1;
            float hn = part[(32 + u1) * 33 + gb] + bhn1;
            float r  = 1.f / (1.f + expf(-(ir1 + hr)));
            float zz = 1.f / (1.f + expf(-(iz1 + hz)));
            float nn = tanhf(in1 + r * hn);
            float hnew = (1.f - zz) * nn + zz * hp1;
            hdst[gb * 512 + j0 + u1] = valid ? __uint_as_float(f2tf(hnew)) : hp1;
            e1 = valid ? hnew : 0.f;
        }

        // publish h(t+1): fence (h stores only in flight), arrive, then slow enc stores
        __threadfence();
        __syncthreads();
        tgt += 32;
        if (tid == 0) atomicAdd(&g_ctr[chain], 1u);
        enc[otok * 1024 + (dir << 9) + j0 + u0] = e0;
        enc[otok * 1024 + (dir << 9) + j0 + u1] = e1;
        if (tid == 0) {
            while (*(volatile unsigned*)&g_ctr[chain] < tgt) { }
        }
        __syncthreads();
    }
}

// ------------------------- row inverse-norms of enc -------------------------
__global__ void k_norm() {
    const float* row = g_enc[blockIdx.y] + (size_t)blockIdx.x * 1024;
    int tid = threadIdx.x;
    float ss = 0.f;
    for (int i = tid; i < 1024; i += 128) { float v = row[i]; ss += v * v; }
    __shared__ float red[4];
    for (int o = 16; o; o >>= 1) ss += __shfl_down_sync(0xffffffffu, ss, o);
    if ((tid & 31) == 0) red[tid >> 5] = ss;
    __syncthreads();
    if (tid == 0) {
        float tot = red[0] + red[1] + red[2] + red[3];
        g_rn[blockIdx.y][blockIdx.x] = tot > 0.f ? rsqrtf(tot) : 0.f;
    }
}

// ------------------------- row / col max+argmax (first-index ties) -------------------------
__global__ void k_rowmax() {
    int row = blockIdx.x * 8 + (threadIdx.x >> 5);
    int l = threadIdx.x & 31;
    const float* s = g_sim + (size_t)row * Lq;
    float bv = -1e30f; int bi = 0;
    for (int j = l; j < Lq; j += 32) {
        float v = s[j];
        if (v > bv) { bv = v; bi = j; }
    }
    for (int o = 16; o; o >>= 1) {
        float ov = __shfl_down_sync(0xffffffffu, bv, o);
        int   oi = __shfl_down_sync(0xffffffffu, bi, o);
        if (ov > bv || (ov == bv && oi < bi)) { bv = ov; bi = oi; }
    }
    if (l == 0) {
        int i = row & 511;
        g_max1[row] = bv;
        g_rel1[row] = (float)(i - bi);
    }
}

__global__ void k_colmax() {
    int id = blockIdx.x * blockDim.x + threadIdx.x;
    int b = id >> 9, j = id & 511;
    const float* s = g_sim + ((size_t)b * Lq) * Lq + j;
    float bv = -1e30f; int bi = 0;
    for (int i = 0; i < Lq; ++i) {
        float v = s[(size_t)i * Lq];
        if (v > bv) { bv = v; bi = i; }
    }
    g_max2[id] = bv;
    g_rel2[id] = (float)(j - bi);
}

// ------------------------- conv branches + maxpool -------------------------
__global__ void k_head(const float* __restrict__ w2p, const float* __restrict__ w3p,
                       const float* __restrict__ w4p, const float* __restrict__ cb,
                       const float* __restrict__ bg, const float* __restrict__ bb,
                       const float* __restrict__ bm, const float* __restrict__ bvv)
{
    int b = blockIdx.x, br = blockIdx.y;
    __shared__ float x0[512], x1[512];
    const float* ms = br ? g_max2 : g_max1;
    const float* rl = br ? g_rel2 : g_rel1;
    for (int i = threadIdx.x; i < 512; i += 128) {
        x0[i] = ms[b * 512 + i];
        x1[i] = rl[b * 512 + i];
    }
    __syncthreads();
    int c = threadIdx.x;
    float* fout = g_feat + b * 768 + br * 384;
    const float* wp[3] = { w2p, w3p, w4p };
    const int kss[3] = { 2, 3, 4 };
    for (int ki = 0; ki < 3; ++ki) {
        int ks = kss[ki];
        float w0[4], w1[4];
        for (int kk = 0; kk < 4; kk++) {
            w0[kk] = kk < ks ? wp[ki][(c * 2 + 0) * ks + kk] : 0.f;
            w1[kk] = kk < ks ? wp[ki][(c * 2 + 1) * ks + kk] : 0.f;
        }
        float s  = bg[ki * 128 + c] / sqrtf(bvv[ki * 128 + c] + 1e-5f);
        float sh = bb[ki * 128 + c] - bm[ki * 128 + c] * s;
        float bias = cb[ki * 128 + c];
        float best = 0.f;
        for (int p = 0; p <= 512 - ks; ++p) {
            float acc = bias;
#pragma unroll
            for (int kk = 0; kk < 4; kk++)
                if (kk < ks) acc += w0[kk] * x0[p + kk] + w1[kk] * x1[p + kk];
            float y = fmaxf(acc * s + sh, 0.f);
            best = fmaxf(best, y);
        }
        fout[ki * 128 + c] = best;
    }
}

// ------------------------- FC + softmax -------------------------
__global__ void k_fc(const float* __restrict__ fcw, const float* __restrict__ fcb,
                     float* __restrict__ out)
{
    int id = threadIdx.x;
    int b = id >> 1, cls = id & 1;
    float acc = fcb[cls];
    const float* f = g_feat + b * 768;
    const float* wrow = fcw + cls * 768;
    for (int k = 0; k < 768; ++k) acc += f[k] * wrow[k];
    float other = __shfl_xor_sync(0xffffffffu, acc, 1);
    float m = fmaxf(acc, other);
    float e = expf(acc - m);
    float ssum = e + expf(other - m);
    out[id] = e / ssum;
}

// ------------------------- launch -------------------------
extern "C" void kernel_launch(void* const* d_in, const int* in_sizes, int n_in,
                              void* d_out, int out_size)
{
    const int* w1  = (const int*)d_in[0];
    const int* w2  = (const int*)d_in[1];
    const int* p1  = (const int*)d_in[2];
    const int* p2  = (const int*)d_in[3];
    const int* ln1 = (const int*)d_in[4];
    const int* ln2 = (const int*)d_in[5];
    const int* tb1 = (const int*)d_in[6];
    const int* te1 = (const int*)d_in[7];
    const int* tb2 = (const int*)d_in[8];
    const int* te2 = (const int*)d_in[9];
    const float* ew   = (const float*)d_in[10];
    const float* ep   = (const float*)d_in[11];
    const float* pe   = (const float*)d_in[12];
    const float* wih  = (const float*)d_in[13];
    const float* whh  = (const float*)d_in[14];
    const float* bih  = (const float*)d_in[15];
    const float* bhh  = (const float*)d_in[16];
    const float* cw0  = (const float*)d_in[17];
    const float* cw1  = (const float*)d_in[18];
    const float* cw2  = (const float*)d_in[19];
    const float* cb   = (const float*)d_in[20];
    const float* bg   = (const float*)d_in[21];
    const float* bb   = (const float*)d_in[22];
    const float* bm   = (const float*)d_in[23];
    const float* bv   = (const float*)d_in[24];
    const float* fcw  = (const float*)d_in[25];
    const float* fcb  = (const float*)d_in[26];
    float* out = (float*)d_out;

    cudaFuncSetAttribute(k_mmt, cudaFuncAttributeMaxDynamicSharedMemorySize, MMT_SMEM);
    cudaFuncSetAttribute(k_gru, cudaFuncAttributeMaxDynamicSharedMemorySize, GRU_SMEM);

    k_init<<<512, 256>>>();
    k_embed<<<dim3(BL, 2), 128>>>(w1, w2, p1, p2, tb1, te1, tb2, te2, ew, ep, pe);
    k_mmt<<<dim3(G3 / 128, BL / 128, 4), 256, MMT_SMEM>>>(0, wih, bih, ln1, ln2);
    k_gru<<<128, 256, GRU_SMEM>>>(whh, bhh, ln1, ln2);
    k_norm<<<dim3(BL, 2), 128>>>();
    k_mmt<<<dim3(Lq / 128, Lq / 128, Bq), 256, MMT_SMEM>>>(1, 0, 0, 0, 0);
    k_rowmax<<<BL / 8, 256>>>();
    k_colmax<<<BL / 256, 256>>>();
    k_head<<<dim3(Bq, 2), 128>>>(cw0, cw1, cw2, cb, bg, bb, bm, bv);
    k_fc<<<1, 64>>>(fcw, fcb, out);
}

// round 11
// speedup vs baseline: 1.4878x; 1.0600x over previous
#include <cuda_runtime.h>
#include <math.h>

#define Bq   32
#define Lq   512
#define Hq   512
#define DIN  832
#define G3   1536
#define BL   (Bq*Lq)          // 16384

// ------------------------- scratch (device globals) -------------------------
__device__ __align__(16) float g_X[2][(size_t)BL * DIN];      // 109 MB
__device__ __align__(16) float g_gi[4][(size_t)BL * G3];      // 402 MB
__device__ __align__(16) float g_h[4][2][Bq * Hq];            // ping-pong hidden [b][k]
__device__ __align__(16) float g_enc[2][(size_t)BL * 1024];   // 134 MB
__device__ __align__(16) float g_sim[(size_t)Bq * Lq * Lq];   // 33.5 MB
__device__ __align__(16) float g_rn[2][BL];                   // 1/row-norm of enc
__device__ __align__(16) float g_max1[BL], g_rel1[BL], g_max2[BL], g_rel2[BL];
__device__ __align__(16) float g_feat[Bq * 768];
__device__ unsigned g_ctr[4];

__device__ __forceinline__ unsigned f2tf(float x) {
    unsigned y;
    asm("cvt.rna.tf32.f32 %0, %1;" : "=r"(y) : "f"(x));
    return y;
}

__device__ __forceinline__ void cpa16(void* dst, const void* src) {
    unsigned d = (unsigned)__cvta_generic_to_shared(dst);
    asm volatile("cp.async.cg.shared.global [%0], [%1], 16;\n" :: "r"(d), "l"(src));
}

// ------------------------- init (reset recurrence state) -------------------------
__global__ void k_init() {
    int i = blockIdx.x * blockDim.x + threadIdx.x;
    if (i < 4 * 2 * Hq * Bq) (&g_h[0][0][0])[i] = 0.f;
    if (i < 4) g_ctr[i] = 0u;
}

// ------------------------- embedding concat -------------------------
__global__ void k_embed(const int* __restrict__ w1, const int* __restrict__ w2,
                        const int* __restrict__ p1, const int* __restrict__ p2,
                        const int* __restrict__ tb1, const int* __restrict__ te1,
                        const int* __restrict__ tb2, const int* __restrict__ te2,
                        const float* __restrict__ ew, const float* __restrict__ ep,
                        const float* __restrict__ pe) {
    int tok  = blockIdx.x;
    int side = blockIdx.y;
    int t    = tok & (Lq - 1);
    const int* w  = side ? w2  : w1;
    const int* pp = side ? p2  : p1;
    const int* tb = side ? tb2 : tb1;
    const int* te = side ? te2 : te1;
    int wi = w[tok], pi = pp[tok], bi = tb[tok], ei = te[tok];
    float* dst = g_X[side] + (size_t)tok * DIN;
    const float* s0 = ew + (size_t)wi * 256;
    const float* s1 = ep + (size_t)pi * 256;
    for (int i = threadIdx.x; i < 256; i += 128) {
        dst[i]       = s0[i];
        dst[256 + i] = s1[i];
    }
    const float* q0 = pe + t * 64;
    const float* q1 = pe + bi * 64;
    const float* q2 = pe + ei * 64;
    const float* q3 = pe + (ei - t) * 64;
    const float* q4 = pe + (t - bi) * 64;
    for (int i = threadIdx.x; i < 64; i += 128) {
        dst[512 + i] = q0[i];
        dst[576 + i] = q1[i];
        dst[640 + i] = q2[i];
        dst[704 + i] = q3[i];
        dst[768 + i] = q4[i];
    }
}

// ------------------------- unified tf32 tensor GEMM (cp.async 3-stage) -------------------------
// mode 0: gi (z=side*2+dir, reversed A gather for dir=1, +bias).
// mode 1: sim (z=batch, A=enc1[z], B=enc2[z], epilogue scales by rn1[m]*rn2[n]).
#define TSTR 36
#define NSTG 3
#define MMT_SLOT (2 * 128 * TSTR)
#define MMT_SMEM (NSTG * MMT_SLOT * 4)

__global__ void __launch_bounds__(256, 2) k_mmt(
    int mode, const float* __restrict__ wih, const float* __restrict__ bih,
    const int* __restrict__ len1, const int* __restrict__ len2)
{
    extern __shared__ float smd[];
    const float *A, *B, *bias = 0;
    float* C;
    int K, N, rev = 0;
    const int* lens = 0;
    int z = blockIdx.z;
    int m0 = blockIdx.y * 128, n0 = blockIdx.x * 128;
    if (mode == 0) {
        int side = z >> 1, dir = z & 1;
        A = g_X[side];
        B = wih + (size_t)dir * G3 * DIN;
        bias = bih + dir * G3;
        C = g_gi[z];
        K = DIN; N = G3;
        lens = side ? len2 : len1;
        rev = dir;
    } else {
        A = g_enc[0] + (size_t)z * Lq * 1024;
        B = g_enc[1] + (size_t)z * Lq * 1024;
        C = g_sim + (size_t)z * Lq * Lq;
        K = 1024; N = Lq;
    }
    int tid = threadIdx.x;

    const float* asrc[4]; const float* bsrc[4]; int cdst[4];
#pragma unroll
    for (int i = 0; i < 4; i++) {
        int c = tid + 256 * i;
        int row = c >> 3, q = c & 7;
        int ar = m0 + row;
        if (rev) {
            int b = ar >> 9, t = ar & 511;
            int Lb = lens[b];
            ar = (b << 9) + ((t < Lb) ? (Lb - 1 - t) : t);
        }
        asrc[i] = A + (size_t)ar * K + q * 4;
        bsrc[i] = B + (size_t)(n0 + row) * K + q * 4;
        cdst[i] = row * TSTR + q * 4;
    }

    int KT = K / 32;
#pragma unroll
    for (int s = 0; s < 2; s++) {
        float* As = smd + s * MMT_SLOT;
        float* Bs = As + 128 * TSTR;
#pragma unroll
        for (int i = 0; i < 4; i++) {
            cpa16(As + cdst[i], asrc[i] + s * 32);
            cpa16(Bs + cdst[i], bsrc[i] + s * 32);
        }
        asm volatile("cp.async.commit_group;\n");
    }

    int lane = tid & 31, warp = tid >> 5;
    int mbase = (warp & 3) * 32, nbase = (warp >> 2) * 64;

    float c[2][8][4];
#pragma unroll
    for (int i = 0; i < 2; i++)
#pragma unroll
        for (int j = 0; j < 8; j++)
#pragma unroll
            for (int r = 0; r < 4; r++) c[i][j][r] = 0.f;

    for (int kt = 0; kt < KT; kt++) {
        asm volatile("cp.async.wait_group 1;\n");
        __syncthreads();
        int slot = kt % NSTG;
        const unsigned* Au = (const unsigned*)(smd + slot * MMT_SLOT);
        const unsigned* Bu = Au + 128 * TSTR;
        if (kt + 2 < KT) {
            int s2 = (kt + 2) % NSTG;
            float* As2 = smd + s2 * MMT_SLOT;
            float* Bs2 = As2 + 128 * TSTR;
#pragma unroll
            for (int i = 0; i < 4; i++) {
                cpa16(As2 + cdst[i], asrc[i] + (kt + 2) * 32);
                cpa16(Bs2 + cdst[i], bsrc[i] + (kt + 2) * 32);
            }
        }
        asm volatile("cp.async.commit_group;\n");

#pragma unroll
        for (int kk = 0; kk < 32; kk += 8) {
            unsigned a[2][4];
#pragma unroll
            for (int i = 0; i < 2; i++) {
                int ao = (mbase + i * 16 + (lane >> 2)) * TSTR + kk + (lane & 3);
                a[i][0] = Au[ao];
                a[i][1] = Au[ao + 8 * TSTR];
                a[i][2] = Au[ao + 4];
                a[i][3] = Au[ao + 8 * TSTR + 4];
            }
#pragma unroll
            for (int j = 0; j < 8; j++) {
                int bo = (nbase + j * 8 + (lane >> 2)) * TSTR + kk + (lane & 3);
                unsigned b0 = Bu[bo], b1 = Bu[bo + 4];
#pragma unroll
                for (int i = 0; i < 2; i++) {
                    asm volatile(
                        "mma.sync.aligned.m16n8k8.row.col.f32.tf32.tf32.f32 "
                        "{%0,%1,%2,%3}, {%4,%5,%6,%7}, {%8,%9}, {%0,%1,%2,%3};"
                        : "+f"(c[i][j][0]), "+f"(c[i][j][1]),
                          "+f"(c[i][j][2]), "+f"(c[i][j][3])
                        : "r"(a[i][0]), "r"(a[i][1]), "r"(a[i][2]), "r"(a[i][3]),
                          "r"(b0), "r"(b1));
                }
            }
        }
    }

    int crow = lane >> 2, ccol = (lane & 3) * 2;
    const float* rn1 = g_rn[0] + z * Lq;
    const float* rn2 = g_rn[1] + z * Lq;
#pragma unroll
    for (int i = 0; i < 2; i++) {
#pragma unroll
        for (int j = 0; j < 8; j++) {
            int m = m0 + mbase + i * 16 + crow;
            int n = n0 + nbase + j * 8 + ccol;
            float v00 = c[i][j][0], v01 = c[i][j][1];
            float v10 = c[i][j][2], v11 = c[i][j][3];
            if (mode == 0) {
                float b0v = bias[n], b1v = bias[n + 1];
                v00 += b0v; v01 += b1v; v10 += b0v; v11 += b1v;
            } else {
                float sm0 = rn1[m], sm1 = rn1[m + 8];
                float sn0 = rn2[n], sn1 = rn2[n + 1];
                v00 *= sm0 * sn0; v01 *= sm0 * sn1;
                v10 *= sm1 * sn0; v11 *= sm1 * sn1;
            }
            C[(size_t)m * N + n]           = v00;
            C[(size_t)m * N + n + 1]       = v01;
            C[(size_t)(m + 8) * N + n]     = v10;
            C[(size_t)(m + 8) * N + n + 1] = v11;
        }
    }
}

// ------------------------- persistent GRU scan (tensor recurrence, smem stage + deferred enc) -------------------------
#define WSTR 516
#define GRU_SMEM ((48 * WSTR + 32 * WSTR + 8 * 48 * 33) * 4)

__global__ void __launch_bounds__(256, 1) k_gru(
    const float* __restrict__ whh, const float* __restrict__ bhh,
    const int* __restrict__ len1, const int* __restrict__ len2)
{
    extern __shared__ unsigned smu[];
    unsigned* Ws  = smu;                                 // [48][WSTR] tf32 bits
    float*    hT  = (float*)(smu + 48 * WSTR);           // [32][WSTR]
    float*    part = hT + 32 * WSTR;                     // [8][48*33]
    const unsigned* hTu = (const unsigned*)hT;

    int chain = blockIdx.x >> 5;
    int blk   = blockIdx.x & 31;
    int side  = chain >> 1, dir = chain & 1;
    int j0    = blk * 16;
    int tid   = threadIdx.x;
    int lane  = tid & 31, warp = tid >> 5;
    const int* lens = side ? len2 : len1;
    const float* gi = g_gi[chain];
    float* enc = g_enc[side];

    for (int i = tid; i < 48 * 512; i += 256) {
        int rr = i >> 9, k = i & 511;
        int g = rr >> 4, u = rr & 15;
        Ws[rr * WSTR + k] = f2tf(whh[((size_t)dir * G3 + g * 512 + j0 + u) * 512 + k]);
    }

    int gb  = tid & 31;
    int u0  = tid >> 5;
    int u1  = u0 + 8;
    int lenb = lens[gb];
    float bhr0 = bhh[dir * G3 +        j0 + u0];
    float bhz0 = bhh[dir * G3 +  512 + j0 + u0];
    float bhn0 = bhh[dir * G3 + 1024 + j0 + u0];
    float bhr1 = bhh[dir * G3 +        j0 + u1];
    float bhz1 = bhh[dir * G3 +  512 + j0 + u1];
    float bhn1 = bhh[dir * G3 + 1024 + j0 + u1];

    int kbase = warp << 6;
    unsigned tgt = 0;
    for (int t = 0; t < Lq; ++t) {
        int p = t & 1;
        // stage h (global [b*512+k] -> smem hT[b][k])
        const float* hsrc = g_h[chain][p];
        for (int i = tid * 4; i < Bq * Hq; i += 1024) {
            float4 v = __ldcg((const float4*)(hsrc + i));
            int b = i >> 9, k = i & 511;
            *(float4*)(hT + b * WSTR + k) = v;
        }
        __syncthreads();

        // prefetch gi gate values (hide scattered loads behind mma)
        size_t tok = (size_t)((gb << 9) | t);
        const float* gp = gi + tok * G3 + j0;
        float ir0 = __ldg(gp + u0), iz0 = __ldg(gp + 512 + u0), in0 = __ldg(gp + 1024 + u0);
        float ir1 = __ldg(gp + u1), iz1 = __ldg(gp + 512 + u1), in1 = __ldg(gp + 1024 + u1);

        // mma: warp's K slice [64w, 64w+64)
        float acc[3][4][4];
#pragma unroll
        for (int mt = 0; mt < 3; mt++)
#pragma unroll
            for (int nt = 0; nt < 4; nt++)
#pragma unroll
                for (int r = 0; r < 4; r++) acc[mt][nt][r] = 0.f;

#pragma unroll
        for (int ks8 = 0; ks8 < 64; ks8 += 8) {
            int k = kbase + ks8;
            unsigned a[3][4];
#pragma unroll
            for (int mt = 0; mt < 3; mt++) {
                int ao = (mt * 16 + (lane >> 2)) * WSTR + k + (lane & 3);
                a[mt][0] = Ws[ao];
                a[mt][1] = Ws[ao + 8 * WSTR];
                a[mt][2] = Ws[ao + 4];
                a[mt][3] = Ws[ao + 8 * WSTR + 4];
            }
            unsigned bfr[4][2];
#pragma unroll
            for (int nt = 0; nt < 4; nt++) {
                int bo = (nt * 8 + (lane >> 2)) * WSTR + k + (lane & 3);
                bfr[nt][0] = hTu[bo];
                bfr[nt][1] = hTu[bo + 4];
            }
#pragma unroll
            for (int mt = 0; mt < 3; mt++)
#pragma unroll
                for (int nt = 0; nt < 4; nt++) {
                    asm volatile(
                        "mma.sync.aligned.m16n8k8.row.col.f32.tf32.tf32.f32 "
                        "{%0,%1,%2,%3}, {%4,%5,%6,%7}, {%8,%9}, {%0,%1,%2,%3};"
                        : "+f"(acc[mt][nt][0]), "+f"(acc[mt][nt][1]),
                          "+f"(acc[mt][nt][2]), "+f"(acc[mt][nt][3])
                        : "r"(a[mt][0]), "r"(a[mt][1]), "r"(a[mt][2]), "r"(a[mt][3]),
                          "r"(bfr[nt][0]), "r"(bfr[nt][1]));
                }
        }
        {
            float* pw = part + warp * (48 * 33);
            int crow = lane >> 2, ccol = 2 * (lane & 3);
#pragma unroll
            for (int mt = 0; mt < 3; mt++)
#pragma unroll
                for (int nt = 0; nt < 4; nt++) {
                    int r0 = mt * 16 + crow;
                    int c0 = nt * 8 + ccol;
                    pw[r0 * 33 + c0]           = acc[mt][nt][0];
                    pw[r0 * 33 + c0 + 1]       = acc[mt][nt][1];
                    pw[(r0 + 8) * 33 + c0]     = acc[mt][nt][2];
                    pw[(r0 + 8) * 33 + c0 + 1] = acc[mt][nt][3];
                }
        }
        __syncthreads();

        for (int i = tid; i < 1536; i += 256) {
            int rr = i >> 5, b = i & 31;
            float s = 0.f;
#pragma unroll
            for (int w = 0; w < 8; w++) s += part[w * (48 * 33) + rr * 33 + b];
            part[rr * 33 + b] = s;
        }
        __syncthreads();

        // gates + h update; enc store deferred past publish
        bool valid = t < lenb;
        int tout = dir ? (valid ? lenb - 1 - t : t) : t;
        size_t otok = (size_t)((gb << 9) | tout);
        float* hdst = g_h[chain][p ^ 1];

        float e0, e1;
        {
            float hr = part[u0 * 33 + gb] + bhr0;
            float hz = part[(16 + u0) * 33 + gb] + bhz0;
            float hn = part[(32 + u0) * 33 + gb] + bhn0;
            float r  = 1.f / (1.f + expf(-(ir0 + hr)));
            float zz = 1.f / (1.f + expf(-(iz0 + hz)));
            float nn = tanhf(in0 + r * hn);
            float hprev = hT[gb * WSTR + j0 + u0];
            float hnew  = (1.f - zz) * nn + zz * hprev;
            hdst[gb * 512 + j0 + u0] = valid ? __uint_as_float(f2tf(hnew)) : hprev;
            e0 = valid ? hnew : 0.f;
        }
        {
            float hr = part[u1 * 33 + gb] + bhr1;
            float hz = part[(16 + u1) * 33 + gb] + bhz1;
            float hn = part[(32 + u1) * 33 + gb] + bhn1;
            float r  = 1.f / (1.f + expf(-(ir1 + hr)));
            float zz = 1.f / (1.f + expf(-(iz1 + hz)));
            float nn = tanhf(in1 + r * hn);
            float hprev = hT[gb * WSTR + j0 + u1];
            float hnew  = (1.f - zz) * nn + zz * hprev;
            hdst[gb * 512 + j0 + u1] = valid ? __uint_as_float(f2tf(hnew)) : hprev;
            e1 = valid ? hnew : 0.f;
        }

        // publish h(t+1): fence (only h stores in flight), arrive, THEN slow enc stores
        __threadfence();
        __syncthreads();
        tgt += 32;
        if (tid == 0) atomicAdd(&g_ctr[chain], 1u);
        enc[otok * 1024 + (dir << 9) + j0 + u0] = e0;
        enc[otok * 1024 + (dir << 9) + j0 + u1] = e1;
        if (tid == 0) {
            while (*(volatile unsigned*)&g_ctr[chain] < tgt) { }
        }
        __syncthreads();
    }
}

// ------------------------- row inverse-norms of enc -------------------------
__global__ void k_norm() {
    const float* row = g_enc[blockIdx.y] + (size_t)blockIdx.x * 1024;
    int tid = threadIdx.x;
    float ss = 0.f;
    for (int i = tid; i < 1024; i += 128) { float v = row[i]; ss += v * v; }
    __shared__ float red[4];
    for (int o = 16; o; o >>= 1) ss += __shfl_down_sync(0xffffffffu, ss, o);
    if ((tid & 31) == 0) red[tid >> 5] = ss;
    __syncthreads();
    if (tid == 0) {
        float tot = red[0] + red[1] + red[2] + red[3];
        g_rn[blockIdx.y][blockIdx.x] = tot > 0.f ? rsqrtf(tot) : 0.f;
    }
}

// ------------------------- row / col max+argmax (first-index ties) -------------------------
__global__ void k_rowmax() {
    int row = blockIdx.x * 8 + (threadIdx.x >> 5);
    int l = threadIdx.x & 31;
    const float* s = g_sim + (size_t)row * Lq;
    float bv = -1e30f; int bi = 0;
    for (int j = l; j < Lq; j += 32) {
        float v = s[j];
        if (v > bv) { bv = v; bi = j; }
    }
    for (int o = 16; o; o >>= 1) {
        float ov = __shfl_down_sync(0xffffffffu, bv, o);
        int   oi = __shfl_down_sync(0xffffffffu, bi, o);
        if (ov > bv || (ov == bv && oi < bi)) { bv = ov; bi = oi; }
    }
    if (l == 0) {
        int i = row & 511;
        g_max1[row] = bv;
        g_rel1[row] = (float)(i - bi);
    }
}

__global__ void k_colmax() {
    int id = blockIdx.x * blockDim.x + threadIdx.x;
    int b = id >> 9, j = id & 511;
    const float* s = g_sim + ((size_t)b * Lq) * Lq + j;
    float bv = -1e30f; int bi = 0;
    for (int i = 0; i < Lq; ++i) {
        float v = s[(size_t)i * Lq];
        if (v > bv) { bv = v; bi = i; }
    }
    g_max2[id] = bv;
    g_rel2[id] = (float)(j - bi);
}

// ------------------------- conv branches + maxpool -------------------------
__global__ void k_head(const float* __restrict__ w2p, const float* __restrict__ w3p,
                       const float* __restrict__ w4p, const float* __restrict__ cb,
                       const float* __restrict__ bg, const float* __restrict__ bb,
                       const float* __restrict__ bm, const float* __restrict__ bvv)
{
    int b = blockIdx.x, br = blockIdx.y;
    __shared__ float x0[512], x1[512];
    const float* ms = br ? g_max2 : g_max1;
    const float* rl = br ? g_rel2 : g_rel1;
    for (int i = threadIdx.x; i < 512; i += 128) {
        x0[i] = ms[b * 512 + i];
        x1[i] = rl[b * 512 + i];
    }
    __syncthreads();
    int c = threadIdx.x;
    float* fout = g_feat + b * 768 + br * 384;
    const float* wp[3] = { w2p, w3p, w4p };
    const int kss[3] = { 2, 3, 4 };
    for (int ki = 0; ki < 3; ++ki) {
        int ks = kss[ki];
        float w0[4], w1[4];
        for (int kk = 0; kk < 4; kk++) {
            w0[kk] = kk < ks ? wp[ki][(c * 2 + 0) * ks + kk] : 0.f;
            w1[kk] = kk < ks ? wp[ki][(c * 2 + 1) * ks + kk] : 0.f;
        }
        float s  = bg[ki * 128 + c] / sqrtf(bvv[ki * 128 + c] + 1e-5f);
        float sh = bb[ki * 128 + c] - bm[ki * 128 + c] * s;
        float bias = cb[ki * 128 + c];
        float best = 0.f;
        for (int p = 0; p <= 512 - ks; ++p) {
            float acc = bias;
#pragma unroll
            for (int kk = 0; kk < 4; kk++)
                if (kk < ks) acc += w0[kk] * x0[p + kk] + w1[kk] * x1[p + kk];
            float y = fmaxf(acc * s + sh, 0.f);
            best = fmaxf(best, y);
        }
        fout[ki * 128 + c] = best;
    }
}

// ------------------------- FC + softmax -------------------------
__global__ void k_fc(const float* __restrict__ fcw, const float* __restrict__ fcb,
                     float* __restrict__ out)
{
    int id = threadIdx.x;
    int b = id >> 1, cls = id & 1;
    float acc = fcb[cls];
    const float* f = g_feat + b * 768;
    const float* wrow = fcw + cls * 768;
    for (int k = 0; k < 768; ++k) acc += f[k] * wrow[k];
    float other = __shfl_xor_sync(0xffffffffu, acc, 1);
    float m = fmaxf(acc, other);
    float e = expf(acc - m);
    float ssum = e + expf(other - m);
    out[id] = e / ssum;
}

// ------------------------- launch -------------------------
extern "C" void kernel_launch(void* const* d_in, const int* in_sizes, int n_in,
                              void* d_out, int out_size)
{
    const int* w1  = (const int*)d_in[0];
    const int* w2  = (const int*)d_in[1];
    const int* p1  = (const int*)d_in[2];
    const int* p2  = (const int*)d_in[3];
    const int* ln1 = (const int*)d_in[4];
    const int* ln2 = (const int*)d_in[5];
    const int* tb1 = (const int*)d_in[6];
    const int* te1 = (const int*)d_in[7];
    const int* tb2 = (const int*)d_in[8];
    const int* te2 = (const int*)d_in[9];
    const float* ew   = (const float*)d_in[10];
    const float* ep   = (const float*)d_in[11];
    const float* pe   = (const float*)d_in[12];
    const float* wih  = (const float*)d_in[13];
    const float* whh  = (const float*)d_in[14];
    const float* bih  = (const float*)d_in[15];
    const float* bhh  = (const float*)d_in[16];
    const float* cw0  = (const float*)d_in[17];
    const float* cw1  = (const float*)d_in[18];
    const float* cw2  = (const float*)d_in[19];
    const float* cb   = (const float*)d_in[20];
    const float* bg   = (const float*)d_in[21];
    const float* bb   = (const float*)d_in[22];
    const float* bm   = (const float*)d_in[23];
    const float* bv   = (const float*)d_in[24];
    const float* fcw  = (const float*)d_in[25];
    const float* fcb  = (const float*)d_in[26];
    float* out = (float*)d_out;

    cudaFuncSetAttribute(k_mmt, cudaFuncAttributeMaxDynamicSharedMemorySize, MMT_SMEM);
    cudaFuncSetAttribute(k_gru, cudaFuncAttributeMaxDynamicSharedMemorySize, GRU_SMEM);

    k_init<<<512, 256>>>();
    k_embed<<<dim3(BL, 2), 128>>>(w1, w2, p1, p2, tb1, te1, tb2, te2, ew, ep, pe);
    k_mmt<<<dim3(G3 / 128, BL / 128, 4), 256, MMT_SMEM>>>(0, wih, bih, ln1, ln2);
    k_gru<<<128, 256, GRU_SMEM>>>(whh, bhh, ln1, ln2);
    k_norm<<<dim3(BL, 2), 128>>>();
    k_mmt<<<dim3(Lq / 128, Lq / 128, Bq), 256, MMT_SMEM>>>(1, 0, 0, 0, 0);
    k_rowmax<<<BL / 8, 256>>>();
    k_colmax<<<BL / 256, 256>>>();
    k_head<<<dim3(Bq, 2), 128>>>(cw0, cw1, cw2, cb, bg, bb, bm, bv);
    k_fc<<<1, 64>>>(fcw, fcb, out);
}

// round 12
// speedup vs baseline: 1.6693x; 1.1220x over previous
#include <cuda_runtime.h>
#include <cuda_bf16.h>
#include <math.h>

#define Bq   32
#define Lq   512
#define Hq   512
#define DIN  832
#define G3   1536
#define BL   (Bq*Lq)          // 16384

// ------------------------- scratch (device globals) -------------------------
__device__ __align__(16) float g_X[2][(size_t)BL * DIN];      // 109 MB
__device__ __align__(16) float g_gi[4][(size_t)BL * G3];      // 402 MB
__device__ __align__(16) unsigned short g_h[4][2][Bq * Hq];   // ping-pong hidden [b][k], bf16
__device__ __align__(16) float g_enc[2][(size_t)BL * 1024];   // 134 MB
__device__ __align__(16) float g_sim[(size_t)Bq * Lq * Lq];   // 33.5 MB
__device__ __align__(16) float g_rn[2][BL];                   // 1/row-norm of enc
__device__ __align__(16) float g_max1[BL], g_rel1[BL], g_max2[BL], g_rel2[BL];
__device__ __align__(16) float g_feat[Bq * 768];
__device__ unsigned g_ctr[4];

__device__ __forceinline__ void cpa16(void* dst, const void* src) {
    unsigned d = (unsigned)__cvta_generic_to_shared(dst);
    asm volatile("cp.async.cg.shared.global [%0], [%1], 16;\n" :: "r"(d), "l"(src));
}

// ------------------------- init (reset recurrence state) -------------------------
__global__ void k_init() {
    int i = blockIdx.x * blockDim.x + threadIdx.x;
    if (i < 4 * 2 * Bq * Hq) (&g_h[0][0][0])[i] = 0;      // bf16 +0.0
    if (i < 4) g_ctr[i] = 0u;
}

// ------------------------- embedding concat -------------------------
__global__ void k_embed(const int* __restrict__ w1, const int* __restrict__ w2,
                        const int* __restrict__ p1, const int* __restrict__ p2,
                        const int* __restrict__ tb1, const int* __restrict__ te1,
                        const int* __restrict__ tb2, const int* __restrict__ te2,
                        const float* __restrict__ ew, const float* __restrict__ ep,
                        const float* __restrict__ pe) {
    int tok  = blockIdx.x;
    int side = blockIdx.y;
    int t    = tok & (Lq - 1);
    const int* w  = side ? w2  : w1;
    const int* pp = side ? p2  : p1;
    const int* tb = side ? tb2 : tb1;
    const int* te = side ? te2 : te1;
    int wi = w[tok], pi = pp[tok], bi = tb[tok], ei = te[tok];
    float* dst = g_X[side] + (size_t)tok * DIN;
    const float* s0 = ew + (size_t)wi * 256;
    const float* s1 = ep + (size_t)pi * 256;
    for (int i = threadIdx.x; i < 256; i += 128) {
        dst[i]       = s0[i];
        dst[256 + i] = s1[i];
    }
    const float* q0 = pe + t * 64;
    const float* q1 = pe + bi * 64;
    const float* q2 = pe + ei * 64;
    const float* q3 = pe + (ei - t) * 64;
    const float* q4 = pe + (t - bi) * 64;
    for (int i = threadIdx.x; i < 64; i += 128) {
        dst[512 + i] = q0[i];
        dst[576 + i] = q1[i];
        dst[640 + i] = q2[i];
        dst[704 + i] = q3[i];
        dst[768 + i] = q4[i];
    }
}

// ------------------------- unified tf32 tensor GEMM (cp.async 3-stage) -------------------------
// mode 0: gi (z=side*2+dir, reversed A gather for dir=1, +bias).
// mode 1: sim (z=batch, A=enc1[z], B=enc2[z], epilogue scales by rn1[m]*rn2[n]).
#define TSTR 36
#define NSTG 3
#define MMT_SLOT (2 * 128 * TSTR)
#define MMT_SMEM (NSTG * MMT_SLOT * 4)

__global__ void __launch_bounds__(256, 2) k_mmt(
    int mode, const float* __restrict__ wih, const float* __restrict__ bih,
    const int* __restrict__ len1, const int* __restrict__ len2)
{
    extern __shared__ float smd[];
    const float *A, *B, *bias = 0;
    float* C;
    int K, N, rev = 0;
    const int* lens = 0;
    int z = blockIdx.z;
    int m0 = blockIdx.y * 128, n0 = blockIdx.x * 128;
    if (mode == 0) {
        int side = z >> 1, dir = z & 1;
        A = g_X[side];
        B = wih + (size_t)dir * G3 * DIN;
        bias = bih + dir * G3;
        C = g_gi[z];
        K = DIN; N = G3;
        lens = side ? len2 : len1;
        rev = dir;
    } else {
        A = g_enc[0] + (size_t)z * Lq * 1024;
        B = g_enc[1] + (size_t)z * Lq * 1024;
        C = g_sim + (size_t)z * Lq * Lq;
        K = 1024; N = Lq;
    }
    int tid = threadIdx.x;

    const float* asrc[4]; const float* bsrc[4]; int cdst[4];
#pragma unroll
    for (int i = 0; i < 4; i++) {
        int c = tid + 256 * i;
        int row = c >> 3, q = c & 7;
        int ar = m0 + row;
        if (rev) {
            int b = ar >> 9, t = ar & 511;
            int Lb = lens[b];
            ar = (b << 9) + ((t < Lb) ? (Lb - 1 - t) : t);
        }
        asrc[i] = A + (size_t)ar * K + q * 4;
        bsrc[i] = B + (size_t)(n0 + row) * K + q * 4;
        cdst[i] = row * TSTR + q * 4;
    }

    int KT = K / 32;
#pragma unroll
    for (int s = 0; s < 2; s++) {
        float* As = smd + s * MMT_SLOT;
        float* Bs = As + 128 * TSTR;
#pragma unroll
        for (int i = 0; i < 4; i++) {
            cpa16(As + cdst[i], asrc[i] + s * 32);
            cpa16(Bs + cdst[i], bsrc[i] + s * 32);
        }
        asm volatile("cp.async.commit_group;\n");
    }

    int lane = tid & 31, warp = tid >> 5;
    int mbase = (warp & 3) * 32, nbase = (warp >> 2) * 64;

    float c[2][8][4];
#pragma unroll
    for (int i = 0; i < 2; i++)
#pragma unroll
        for (int j = 0; j < 8; j++)
#pragma unroll
            for (int r = 0; r < 4; r++) c[i][j][r] = 0.f;

    for (int kt = 0; kt < KT; kt++) {
        asm volatile("cp.async.wait_group 1;\n");
        __syncthreads();
        int slot = kt % NSTG;
        const unsigned* Au = (const unsigned*)(smd + slot * MMT_SLOT);
        const unsigned* Bu = Au + 128 * TSTR;
        if (kt + 2 < KT) {
            int s2 = (kt + 2) % NSTG;
            float* As2 = smd + s2 * MMT_SLOT;
            float* Bs2 = As2 + 128 * TSTR;
#pragma unroll
            for (int i = 0; i < 4; i++) {
                cpa16(As2 + cdst[i], asrc[i] + (kt + 2) * 32);
                cpa16(Bs2 + cdst[i], bsrc[i] + (kt + 2) * 32);
            }
        }
        asm volatile("cp.async.commit_group;\n");

#pragma unroll
        for (int kk = 0; kk < 32; kk += 8) {
            unsigned a[2][4];
#pragma unroll
            for (int i = 0; i < 2; i++) {
                int ao = (mbase + i * 16 + (lane >> 2)) * TSTR + kk + (lane & 3);
                a[i][0] = Au[ao];
                a[i][1] = Au[ao + 8 * TSTR];
                a[i][2] = Au[ao + 4];
                a[i][3] = Au[ao + 8 * TSTR + 4];
            }
#pragma unroll
            for (int j = 0; j < 8; j++) {
                int bo = (nbase + j * 8 + (lane >> 2)) * TSTR + kk + (lane & 3);
                unsigned b0 = Bu[bo], b1 = Bu[bo + 4];
#pragma unroll
                for (int i = 0; i < 2; i++) {
                    asm volatile(
                        "mma.sync.aligned.m16n8k8.row.col.f32.tf32.tf32.f32 "
                        "{%0,%1,%2,%3}, {%4,%5,%6,%7}, {%8,%9}, {%0,%1,%2,%3};"
                        : "+f"(c[i][j][0]), "+f"(c[i][j][1]),
                          "+f"(c[i][j][2]), "+f"(c[i][j][3])
                        : "r"(a[i][0]), "r"(a[i][1]), "r"(a[i][2]), "r"(a[i][3]),
                          "r"(b0), "r"(b1));
                }
            }
        }
    }

    int crow = lane >> 2, ccol = (lane & 3) * 2;
    const float* rn1 = g_rn[0] + z * Lq;
    const float* rn2 = g_rn[1] + z * Lq;
#pragma unroll
    for (int i = 0; i < 2; i++) {
#pragma unroll
        for (int j = 0; j < 8; j++) {
            int m = m0 + mbase + i * 16 + crow;
            int n = n0 + nbase + j * 8 + ccol;
            float v00 = c[i][j][0], v01 = c[i][j][1];
            float v10 = c[i][j][2], v11 = c[i][j][3];
            if (mode == 0) {
                float b0v = bias[n], b1v = bias[n + 1];
                v00 += b0v; v01 += b1v; v10 += b0v; v11 += b1v;
            } else {
                float sm0 = rn1[m], sm1 = rn1[m + 8];
                float sn0 = rn2[n], sn1 = rn2[n + 1];
                v00 *= sm0 * sn0; v01 *= sm0 * sn1;
                v10 *= sm1 * sn0; v11 *= sm1 * sn1;
            }
            C[(size_t)m * N + n]           = v00;
            C[(size_t)m * N + n + 1]       = v01;
            C[(size_t)(m + 8) * N + n]     = v10;
            C[(size_t)(m + 8) * N + n + 1] = v11;
        }
    }
}

// ------------------------- persistent GRU scan (bf16 tensor recurrence) -------------------------
// gh[48,32] = Ws[48,512] @ h[32,512]^T via mma.m16n8k16.bf16, fp32 accum.
// smem rows stride 520 bf16 = 260 words => fragment bank = 4r+q, conflict-free.
#define HSTR 520
#define GRU_SMEM (48 * HSTR * 2 + 32 * HSTR * 2 + 8 * 48 * 33 * 4)

__global__ void __launch_bounds__(256, 1) k_gru(
    const float* __restrict__ whh, const float* __restrict__ bhh,
    const int* __restrict__ len1, const int* __restrict__ len2)
{
    extern __shared__ unsigned short sm16[];
    unsigned short* Ws16 = sm16;                          // [48][HSTR] bf16
    unsigned short* hT16 = sm16 + 48 * HSTR;              // [32][HSTR] bf16
    float* part = (float*)(sm16 + 48 * HSTR + 32 * HSTR); // [8][48*33] fp32

    int chain = blockIdx.x >> 5;
    int blk   = blockIdx.x & 31;
    int side  = chain >> 1, dir = chain & 1;
    int j0    = blk * 16;
    int tid   = threadIdx.x;
    int lane  = tid & 31, warp = tid >> 5;
    const int* lens = side ? len2 : len1;
    const float* gi = g_gi[chain];
    float* enc = g_enc[side];

    // load + convert Whh slice to bf16: rr = g*16+u <-> whh row dir*1536 + g*512 + j0 + u
    for (int i = tid; i < 48 * 512; i += 256) {
        int rr = i >> 9, k = i & 511;
        int g = rr >> 4, u = rr & 15;
        __nv_bfloat16 v = __float2bfloat16(whh[((size_t)dir * G3 + g * 512 + j0 + u) * 512 + k]);
        Ws16[rr * HSTR + k] = *(unsigned short*)&v;
    }

    int gb  = tid & 31;
    int u0  = tid >> 5;
    int u1  = u0 + 8;
    int lenb = lens[gb];
    float bhr0 = bhh[dir * G3 +        j0 + u0];
    float bhz0 = bhh[dir * G3 +  512 + j0 + u0];
    float bhn0 = bhh[dir * G3 + 1024 + j0 + u0];
    float bhr1 = bhh[dir * G3 +        j0 + u1];
    float bhz1 = bhh[dir * G3 +  512 + j0 + u1];
    float bhn1 = bhh[dir * G3 + 1024 + j0 + u1];

    int kbase = warp << 6;                  // warp's K slice [64w, 64w+64)
    unsigned tgt = 0;
    for (int t = 0; t < Lq; ++t) {
        int p = t & 1;
        // stage h (bf16 [b*512+k] -> smem hT16[b][k]); 2048 uint4 / 256 thr = 8 each
        const unsigned short* hsrc = g_h[chain][p];
        for (int i = tid; i < 2048; i += 256) {
            uint4 v = __ldcg((const uint4*)(hsrc + i * 8));
            int b = i >> 6, k = (i & 63) * 8;
            *(uint4*)(hT16 + b * HSTR + k) = v;
        }
        __syncthreads();

        // prefetch gi gate values (hide scattered loads behind mma)
        size_t tok = (size_t)((gb << 9) | t);
        const float* gp = gi + tok * G3 + j0;
        float ir0 = __ldg(gp + u0), iz0 = __ldg(gp + 512 + u0), in0 = __ldg(gp + 1024 + u0);
        float ir1 = __ldg(gp + u1), iz1 = __ldg(gp + 512 + u1), in1 = __ldg(gp + 1024 + u1);

        // mma: 4 ksteps of k16 over warp's slice
        float acc[3][4][4];
#pragma unroll
        for (int mt = 0; mt < 3; mt++)
#pragma unroll
            for (int nt = 0; nt < 4; nt++)
#pragma unroll
                for (int r = 0; r < 4; r++) acc[mt][nt][r] = 0.f;

        const unsigned* Wsu = (const unsigned*)Ws16;
        const unsigned* hTu = (const unsigned*)hT16;
#pragma unroll
        for (int ks = 0; ks < 4; ks++) {
            int k0 = kbase + ks * 16;
            int kq = (k0 >> 1) + (lane & 3);           // word offset within row
            unsigned a[3][4];
#pragma unroll
            for (int mt = 0; mt < 3; mt++) {
                int ao = (mt * 16 + (lane >> 2)) * 260 + kq;
                a[mt][0] = Wsu[ao];
                a[mt][1] = Wsu[ao + 8 * 260];
                a[mt][2] = Wsu[ao + 4];
                a[mt][3] = Wsu[ao + 8 * 260 + 4];
            }
            unsigned bfr[4][2];
#pragma unroll
            for (int nt = 0; nt < 4; nt++) {
                int bo = (nt * 8 + (lane >> 2)) * 260 + kq;
                bfr[nt][0] = hTu[bo];
                bfr[nt][1] = hTu[bo + 4];
            }
#pragma unroll
            for (int mt = 0; mt < 3; mt++)
#pragma unroll
                for (int nt = 0; nt < 4; nt++) {
                    asm volatile(
                        "mma.sync.aligned.m16n8k16.row.col.f32.bf16.bf16.f32 "
                        "{%0,%1,%2,%3}, {%4,%5,%6,%7}, {%8,%9}, {%0,%1,%2,%3};"
                        : "+f"(acc[mt][nt][0]), "+f"(acc[mt][nt][1]),
                          "+f"(acc[mt][nt][2]), "+f"(acc[mt][nt][3])
                        : "r"(a[mt][0]), "r"(a[mt][1]), "r"(a[mt][2]), "r"(a[mt][3]),
                          "r"(bfr[nt][0]), "r"(bfr[nt][1]));
                }
        }
        {
            float* pw = part + warp * (48 * 33);
            int crow = lane >> 2, ccol = 2 * (lane & 3);
#pragma unroll
            for (int mt = 0; mt < 3; mt++)
#pragma unroll
                for (int nt = 0; nt < 4; nt++) {
                    int r0 = mt * 16 + crow;
                    int c0 = nt * 8 + ccol;
                    pw[r0 * 33 + c0]           = acc[mt][nt][0];
                    pw[r0 * 33 + c0 + 1]       = acc[mt][nt][1];
                    pw[(r0 + 8) * 33 + c0]     = acc[mt][nt][2];
                    pw[(r0 + 8) * 33 + c0 + 1] = acc[mt][nt][3];
                }
        }
        __syncthreads();

        for (int i = tid; i < 1536; i += 256) {
            int rr = i >> 5, b = i & 31;
            float s = 0.f;
#pragma unroll
            for (int w = 0; w < 8; w++) s += part[w * (48 * 33) + rr * 33 + b];
            part[rr * 33 + b] = s;
        }
        __syncthreads();

        // gates + h update; enc store deferred past publish
        bool valid = t < lenb;
        int tout = dir ? (valid ? lenb - 1 - t : t) : t;
        size_t otok = (size_t)((gb << 9) | tout);
        unsigned short* hdst = g_h[chain][p ^ 1];

        float e0, e1;
        {
            unsigned short hpb = hT16[gb * HSTR + j0 + u0];
            float hprev = __bfloat162float(*(__nv_bfloat16*)&hpb);
            float hr = part[u0 * 33 + gb] + bhr0;
            float hz = part[(16 + u0) * 33 + gb] + bhz0;
            float hn = part[(32 + u0) * 33 + gb] + bhn0;
            float r  = 1.f / (1.f + expf(-(ir0 + hr)));
            float zz = 1.f / (1.f + expf(-(iz0 + hz)));
            float nn = tanhf(in0 + r * hn);
            float hnew = (1.f - zz) * nn + zz * hprev;
            __nv_bfloat16 hb = __float2bfloat16(hnew);
            hdst[gb * 512 + j0 + u0] = valid ? *(unsigned short*)&hb : hpb;
            e0 = valid ? hnew : 0.f;
        }
        {
            unsigned short hpb = hT16[gb * HSTR + j0 + u1];
            float hprev = __bfloat162float(*(__nv_bfloat16*)&hpb);
            float hr = part[u1 * 33 + gb] + bhr1;
            float hz = part[(16 + u1) * 33 + gb] + bhz1;
            float hn = part[(32 + u1) * 33 + gb] + bhn1;
            float r  = 1.f / (1.f + expf(-(ir1 + hr)));
            float zz = 1.f / (1.f + expf(-(iz1 + hz)));
            float nn = tanhf(in1 + r * hn);
            float hnew = (1.f - zz) * nn + zz * hprev;
            __nv_bfloat16 hb = __float2bfloat16(hnew);
            hdst[gb * 512 + j0 + u1] = valid ? *(unsigned short*)&hb : hpb;
            e1 = valid ? hnew : 0.f;
        }

        // publish h(t+1): fence (only h stores in flight), arrive, THEN slow enc stores
        __threadfence();
        __syncthreads();
        tgt += 32;
        if (tid == 0) atomicAdd(&g_ctr[chain], 1u);
        enc[otok * 1024 + (dir << 9) + j0 + u0] = e0;
        enc[otok * 1024 + (dir << 9) + j0 + u1] = e1;
        if (tid == 0) {
            while (*(volatile unsigned*)&g_ctr[chain] < tgt) { }
        }
        __syncthreads();
    }
}

// ------------------------- row inverse-norms of enc -------------------------
__global__ void k_norm() {
    const float* row = g_enc[blockIdx.y] + (size_t)blockIdx.x * 1024;
    int tid = threadIdx.x;
    float ss = 0.f;
    for (int i = tid; i < 1024; i += 128) { float v = row[i]; ss += v * v; }
    __shared__ float red[4];
    for (int o = 16; o; o >>= 1) ss += __shfl_down_sync(0xffffffffu, ss, o);
    if ((tid & 31) == 0) red[tid >> 5] = ss;
    __syncthreads();
    if (tid == 0) {
        float tot = red[0] + red[1] + red[2] + red[3];
        g_rn[blockIdx.y][blockIdx.x] = tot > 0.f ? rsqrtf(tot) : 0.f;
    }
}

// ------------------------- row / col max+argmax (first-index ties) -------------------------
__global__ void k_rowmax() {
    int row = blockIdx.x * 8 + (threadIdx.x >> 5);
    int l = threadIdx.x & 31;
    const float* s = g_sim + (size_t)row * Lq;
    float bv = -1e30f; int bi = 0;
    for (int j = l; j < Lq; j += 32) {
        float v = s[j];
        if (v > bv) { bv = v; bi = j; }
    }
    for (int o = 16; o; o >>= 1) {
        float ov = __shfl_down_sync(0xffffffffu, bv, o);
        int   oi = __shfl_down_sync(0xffffffffu, bi, o);
        if (ov > bv || (ov == bv && oi < bi)) { bv = ov; bi = oi; }
    }
    if (l == 0) {
        int i = row & 511;
        g_max1[row] = bv;
        g_rel1[row] = (float)(i - bi);
    }
}

__global__ void k_colmax() {
    int id = blockIdx.x * blockDim.x + threadIdx.x;
    int b = id >> 9, j = id & 511;
    const float* s = g_sim + ((size_t)b * Lq) * Lq + j;
    float bv = -1e30f; int bi = 0;
    for (int i = 0; i < Lq; ++i) {
        float v = s[(size_t)i * Lq];
        if (v > bv) { bv = v; bi = i; }
    }
    g_max2[id] = bv;
    g_rel2[id] = (float)(j - bi);
}

// ------------------------- conv branches + maxpool -------------------------
__global__ void k_head(const float* __restrict__ w2p, const float* __restrict__ w3p,
                       const float* __restrict__ w4p, const float* __restrict__ cb,
                       const float* __restrict__ bg, const float* __restrict__ bb,
                       const float* __restrict__ bm, const float* __restrict__ bvv)
{
    int b = blockIdx.x, br = blockIdx.y;
    __shared__ float x0[512], x1[512];
    const float* ms = br ? g_max2 : g_max1;
    const float* rl = br ? g_rel2 : g_rel1;
    for (int i = threadIdx.x; i < 512; i += 128) {
        x0[i] = ms[b * 512 + i];
        x1[i] = rl[b * 512 + i];
    }
    __syncthreads();
    int c = threadIdx.x;
    float* fout = g_feat + b * 768 + br * 384;
    const float* wp[3] = { w2p, w3p, w4p };
    const int kss[3] = { 2, 3, 4 };
    for (int ki = 0; ki < 3; ++ki) {
        int ks = kss[ki];
        float w0[4], w1[4];
        for (int kk = 0; kk < 4; kk++) {
            w0[kk] = kk < ks ? wp[ki][(c * 2 + 0) * ks + kk] : 0.f;
            w1[kk] = kk < ks ? wp[ki][(c * 2 + 1) * ks + kk] : 0.f;
        }
        float s  = bg[ki * 128 + c] / sqrtf(bvv[ki * 128 + c] + 1e-5f);
        float sh = bb[ki * 128 + c] - bm[ki * 128 + c] * s;
        float bias = cb[ki * 128 + c];
        float best = 0.f;
        for (int p = 0; p <= 512 - ks; ++p) {
            float acc = bias;
#pragma unroll
            for (int kk = 0; kk < 4; kk++)
                if (kk < ks) acc += w0[kk] * x0[p + kk] + w1[kk] * x1[p + kk];
            float y = fmaxf(acc * s + sh, 0.f);
            best = fmaxf(best, y);
        }
        fout[ki * 128 + c] = best;
    }
}

// ------------------------- FC + softmax -------------------------
__global__ void k_fc(const float* __restrict__ fcw, const float* __restrict__ fcb,
                     float* __restrict__ out)
{
    int id = threadIdx.x;
    int b = id >> 1, cls = id & 1;
    float acc = fcb[cls];
    const float* f = g_feat + b * 768;
    const float* wrow = fcw + cls * 768;
    for (int k = 0; k < 768; ++k) acc += f[k] * wrow[k];
    float other = __shfl_xor_sync(0xffffffffu, acc, 1);
    float m = fmaxf(acc, other);
    float e = expf(acc - m);
    float ssum = e + expf(other - m);
    out[id] = e / ssum;
}

// ------------------------- launch -------------------------
extern "C" void kernel_launch(void* const* d_in, const int* in_sizes, int n_in,
                              void* d_out, int out_size)
{
    const int* w1  = (const int*)d_in[0];
    const int* w2  = (const int*)d_in[1];
    const int* p1  = (const int*)d_in[2];
    const int* p2  = (const int*)d_in[3];
    const int* ln1 = (const int*)d_in[4];
    const int* ln2 = (const int*)d_in[5];
    const int* tb1 = (const int*)d_in[6];
    const int* te1 = (const int*)d_in[7];
    const int* tb2 = (const int*)d_in[8];
    const int* te2 = (const int*)d_in[9];
    const float* ew   = (const float*)d_in[10];
    const float* ep   = (const float*)d_in[11];
    const float* pe   = (const float*)d_in[12];
    const float* wih  = (const float*)d_in[13];
    const float* whh  = (const float*)d_in[14];
    const float* bih  = (const float*)d_in[15];
    const float* bhh  = (const float*)d_in[16];
    const float* cw0  = (const float*)d_in[17];
    const float* cw1  = (const float*)d_in[18];
    const float* cw2  = (const float*)d_in[19];
    const float* cb   = (const float*)d_in[20];
    const float* bg   = (const float*)d_in[21];
    const float* bb   = (const float*)d_in[22];
    const float* bm   = (const float*)d_in[23];
    const float* bv   = (const float*)d_in[24];
    const float* fcw  = (const float*)d_in[25];
    const float* fcb  = (const float*)d_in[26];
    float* out = (float*)d_out;

    cudaFuncSetAttribute(k_mmt, cudaFuncAttributeMaxDynamicSharedMemorySize, MMT_SMEM);
    cudaFuncSetAttribute(k_gru, cudaFuncAttributeMaxDynamicSharedMemorySize, GRU_SMEM);

    k_init<<<512, 256>>>();
    k_embed<<<dim3(BL, 2), 128>>>(w1, w2, p1, p2, tb1, te1, tb2, te2, ew, ep, pe);
    k_mmt<<<dim3(G3 / 128, BL / 128, 4), 256, MMT_SMEM>>>(0, wih, bih, ln1, ln2);
    k_gru<<<128, 256, GRU_SMEM>>>(whh, bhh, ln1, ln2);
    k_norm<<<dim3(BL, 2), 128>>>();
    k_mmt<<<dim3(Lq / 128, Lq / 128, Bq), 256, MMT_SMEM>>>(1, 0, 0, 0, 0);
    k_rowmax<<<BL / 8, 256>>>();
    k_colmax<<<BL / 256, 256>>>();
    k_head<<<dim3(Bq, 2), 128>>>(cw0, cw1, cw2, cb, bg, bb, bm, bv);
    k_fc<<<1, 64>>>(fcw, fcb, out);
}

// round 13
// speedup vs baseline: 1.8959x; 1.1357x over previous
#include <cuda_runtime.h>
#include <cuda_bf16.h>
#include <math.h>

#define Bq   32
#define Lq   512
#define Hq   512
#define DIN  832
#define G3   1536
#define BL   (Bq*Lq)          // 16384

// ------------------------- scratch (device globals) -------------------------
__device__ __align__(16) unsigned short g_X[2][(size_t)BL * DIN];   // bf16, 55 MB
__device__ __align__(16) unsigned short g_w16[2 * G3 * DIN];        // bf16 wih copy
__device__ __align__(16) float g_gi[4][(size_t)BL * G3];            // 402 MB
__device__ __align__(16) unsigned short g_h[4][2][Bq * Hq];         // bf16 hidden [b][k]
__device__ __align__(16) float g_enc[2][(size_t)BL * 1024];         // 134 MB
__device__ __align__(16) float g_sim[(size_t)Bq * Lq * Lq];         // 33.5 MB
__device__ __align__(16) float g_rn[2][BL];                         // 1/row-norm of enc
__device__ __align__(16) float g_max1[BL], g_rel1[BL], g_max2[BL], g_rel2[BL];
__device__ __align__(16) float g_feat[Bq * 768];
__device__ unsigned g_ctr[4];

__device__ __forceinline__ void cpa16(void* dst, const void* src) {
    unsigned d = (unsigned)__cvta_generic_to_shared(dst);
    asm volatile("cp.async.cg.shared.global [%0], [%1], 16;\n" :: "r"(d), "l"(src));
}
__device__ __forceinline__ unsigned short f2b(float x) {
    __nv_bfloat16 v = __float2bfloat16(x);
    return *(unsigned short*)&v;
}

// ------------------------- init -------------------------
__global__ void k_init() {
    int i = blockIdx.x * blockDim.x + threadIdx.x;
    if (i < 4 * 2 * Bq * Hq) (&g_h[0][0][0])[i] = 0;
    if (i < 4) g_ctr[i] = 0u;
}

// ------------------------- wih -> bf16 copy -------------------------
__global__ void k_cvtw(const float* __restrict__ wih) {
    int i = blockIdx.x * 256 + threadIdx.x;          // 2*G3*DIN = 2,555,904
    g_w16[i] = f2b(wih[i]);
}

// ------------------------- embedding concat (bf16 X) -------------------------
__global__ void k_embed(const int* __restrict__ w1, const int* __restrict__ w2,
                        const int* __restrict__ p1, const int* __restrict__ p2,
                        const int* __restrict__ tb1, const int* __restrict__ te1,
                        const int* __restrict__ tb2, const int* __restrict__ te2,
                        const float* __restrict__ ew, const float* __restrict__ ep,
                        const float* __restrict__ pe) {
    int tok  = blockIdx.x;
    int side = blockIdx.y;
    int t    = tok & (Lq - 1);
    const int* w  = side ? w2  : w1;
    const int* pp = side ? p2  : p1;
    const int* tb = side ? tb2 : tb1;
    const int* te = side ? te2 : te1;
    int wi = w[tok], pi = pp[tok], bi = tb[tok], ei = te[tok];
    unsigned short* dst = g_X[side] + (size_t)tok * DIN;
    const float* s0 = ew + (size_t)wi * 256;
    const float* s1 = ep + (size_t)pi * 256;
    for (int i = threadIdx.x; i < 256; i += 128) {
        dst[i]       = f2b(s0[i]);
        dst[256 + i] = f2b(s1[i]);
    }
    const float* q0 = pe + t * 64;
    const float* q1 = pe + bi * 64;
    const float* q2 = pe + ei * 64;
    const float* q3 = pe + (ei - t) * 64;
    const float* q4 = pe + (t - bi) * 64;
    for (int i = threadIdx.x; i < 64; i += 128) {
        dst[512 + i] = f2b(q0[i]);
        dst[576 + i] = f2b(q1[i]);
        dst[640 + i] = f2b(q2[i]);
        dst[704 + i] = f2b(q3[i]);
        dst[768 + i] = f2b(q4[i]);
    }
}

// ------------------------- bf16 gi GEMM (cp.async 3-stage, m16n8k16) -------------------------
// C[16384,1536] = X[16384,832] * wih[1536,832]^T + bias, z = side*2+dir,
// reversed A-row gather for dir=1. Row stride 20 words -> conflict-free fragments.
#define NSTG 3
#define BSTR 20
#define G16_SLOT (2 * 128 * BSTR)
#define G16_SMEM (NSTG * G16_SLOT * 4)

__global__ void __launch_bounds__(256, 2) k_gemm16(
    const float* __restrict__ bih,
    const int* __restrict__ len1, const int* __restrict__ len2)
{
    extern __shared__ unsigned smg[];
    int z = blockIdx.z;
    int side = z >> 1, dir = z & 1;
    const unsigned short* A = g_X[side];
    const unsigned short* B = g_w16 + (size_t)dir * G3 * DIN;
    const float* bias = bih + dir * G3;
    float* C = g_gi[z];
    const int* lens = side ? len2 : len1;
    int tid = threadIdx.x;
    int m0 = blockIdx.y * 128, n0 = blockIdx.x * 128;

    // copy geometry: per k-tile each row needs 32 bf16 = 4 x 16B chunks; 512 chunks/operand
    const unsigned short* asrc[2]; const unsigned short* bsrc[2]; int cdst[2];
#pragma unroll
    for (int i = 0; i < 2; i++) {
        int c = tid + 256 * i;              // 0..511
        int row = c >> 2, q = c & 3;
        int ar = m0 + row;
        if (dir) {
            int b = ar >> 9, t = ar & 511;
            int Lb = lens[b];
            ar = (b << 9) + ((t < Lb) ? (Lb - 1 - t) : t);
        }
        asrc[i] = A + (size_t)ar * DIN + q * 8;
        bsrc[i] = B + (size_t)(n0 + row) * DIN + q * 8;
        cdst[i] = row * BSTR + q * 4;
    }

    const int KT = DIN / 32;                // 26
#pragma unroll
    for (int s = 0; s < 2; s++) {
        unsigned* As = smg + s * G16_SLOT;
        unsigned* Bs = As + 128 * BSTR;
#pragma unroll
        for (int i = 0; i < 2; i++) {
            cpa16(As + cdst[i], asrc[i] + s * 32);
            cpa16(Bs + cdst[i], bsrc[i] + s * 32);
        }
        asm volatile("cp.async.commit_group;\n");
    }

    int lane = tid & 31, warp = tid >> 5;
    int mbase = (warp & 3) * 32, nbase = (warp >> 2) * 64;

    float c[2][8][4];
#pragma unroll
    for (int i = 0; i < 2; i++)
#pragma unroll
        for (int j = 0; j < 8; j++)
#pragma unroll
            for (int r = 0; r < 4; r++) c[i][j][r] = 0.f;

    for (int kt = 0; kt < KT; kt++) {
        asm volatile("cp.async.wait_group 1;\n");
        __syncthreads();
        const unsigned* Au = smg + (kt % NSTG) * G16_SLOT;
        const unsigned* Bu = Au + 128 * BSTR;
        if (kt + 2 < KT) {
            unsigned* As2 = smg + ((kt + 2) % NSTG) * G16_SLOT;
            unsigned* Bs2 = As2 + 128 * BSTR;
#pragma unroll
            for (int i = 0; i < 2; i++) {
                cpa16(As2 + cdst[i], asrc[i] + (kt + 2) * 32);
                cpa16(Bs2 + cdst[i], bsrc[i] + (kt + 2) * 32);
            }
        }
        asm volatile("cp.async.commit_group;\n");

#pragma unroll
        for (int ks = 0; ks < 2; ks++) {
            int kw = ks * 8 + (lane & 3);
            unsigned a[2][4];
#pragma unroll
            for (int i = 0; i < 2; i++) {
                int ao = (mbase + i * 16 + (lane >> 2)) * BSTR + kw;
                a[i][0] = Au[ao];
                a[i][1] = Au[ao + 8 * BSTR];
                a[i][2] = Au[ao + 4];
                a[i][3] = Au[ao + 8 * BSTR + 4];
            }
#pragma unroll
            for (int j = 0; j < 8; j++) {
                int bo = (nbase + j * 8 + (lane >> 2)) * BSTR + kw;
                unsigned b0 = Bu[bo], b1 = Bu[bo + 4];
#pragma unroll
                for (int i = 0; i < 2; i++) {
                    asm volatile(
                        "mma.sync.aligned.m16n8k16.row.col.f32.bf16.bf16.f32 "
                        "{%0,%1,%2,%3}, {%4,%5,%6,%7}, {%8,%9}, {%0,%1,%2,%3};"
                        : "+f"(c[i][j][0]), "+f"(c[i][j][1]),
                          "+f"(c[i][j][2]), "+f"(c[i][j][3])
                        : "r"(a[i][0]), "r"(a[i][1]), "r"(a[i][2]), "r"(a[i][3]),
                          "r"(b0), "r"(b1));
                }
            }
        }
    }

    int crow = lane >> 2, ccol = (lane & 3) * 2;
#pragma unroll
    for (int i = 0; i < 2; i++) {
#pragma unroll
        for (int j = 0; j < 8; j++) {
            int m = m0 + mbase + i * 16 + crow;
            int n = n0 + nbase + j * 8 + ccol;
            float b0v = bias[n], b1v = bias[n + 1];
            C[(size_t)m * G3 + n]           = c[i][j][0] + b0v;
            C[(size_t)m * G3 + n + 1]       = c[i][j][1] + b1v;
            C[(size_t)(m + 8) * G3 + n]     = c[i][j][2] + b0v;
            C[(size_t)(m + 8) * G3 + n + 1] = c[i][j][3] + b1v;
        }
    }
}

// ------------------------- sim GEMM (raw-fp32-as-tf32, cp.async 3-stage) -------------------------
#define TSTR 36
#define SIM_SLOT (2 * 128 * TSTR)
#define SIM_SMEM (NSTG * SIM_SLOT * 4)

__global__ void __launch_bounds__(256, 2) k_sim()
{
    extern __shared__ float smd[];
    int z = blockIdx.z;
    const float* A = g_enc[0] + (size_t)z * Lq * 1024;
    const float* B = g_enc[1] + (size_t)z * Lq * 1024;
    float* C = g_sim + (size_t)z * Lq * Lq;
    const int K = 1024, N = Lq;
    int tid = threadIdx.x;
    int m0 = blockIdx.y * 128, n0 = blockIdx.x * 128;

    const float* asrc[4]; const float* bsrc[4]; int cdst[4];
#pragma unroll
    for (int i = 0; i < 4; i++) {
        int c = tid + 256 * i;
        int row = c >> 3, q = c & 7;
        asrc[i] = A + (size_t)(m0 + row) * K + q * 4;
        bsrc[i] = B + (size_t)(n0 + row) * K + q * 4;
        cdst[i] = row * TSTR + q * 4;
    }

    const int KT = K / 32;
#pragma unroll
    for (int s = 0; s < 2; s++) {
        float* As = smd + s * SIM_SLOT;
        float* Bs = As + 128 * TSTR;
#pragma unroll
        for (int i = 0; i < 4; i++) {
            cpa16(As + cdst[i], asrc[i] + s * 32);
            cpa16(Bs + cdst[i], bsrc[i] + s * 32);
        }
        asm volatile("cp.async.commit_group;\n");
    }

    int lane = tid & 31, warp = tid >> 5;
    int mbase = (warp & 3) * 32, nbase = (warp >> 2) * 64;

    float c[2][8][4];
#pragma unroll
    for (int i = 0; i < 2; i++)
#pragma unroll
        for (int j = 0; j < 8; j++)
#pragma unroll
            for (int r = 0; r < 4; r++) c[i][j][r] = 0.f;

    for (int kt = 0; kt < KT; kt++) {
        asm volatile("cp.async.wait_group 1;\n");
        __syncthreads();
        const unsigned* Au = (const unsigned*)(smd + (kt % NSTG) * SIM_SLOT);
        const unsigned* Bu = Au + 128 * TSTR;
        if (kt + 2 < KT) {
            float* As2 = smd + ((kt + 2) % NSTG) * SIM_SLOT;
            float* Bs2 = As2 + 128 * TSTR;
#pragma unroll
            for (int i = 0; i < 4; i++) {
                cpa16(As2 + cdst[i], asrc[i] + (kt + 2) * 32);
                cpa16(Bs2 + cdst[i], bsrc[i] + (kt + 2) * 32);
            }
        }
        asm volatile("cp.async.commit_group;\n");

#pragma unroll
        for (int kk = 0; kk < 32; kk += 8) {
            unsigned a[2][4];
#pragma unroll
            for (int i = 0; i < 2; i++) {
                int ao = (mbase + i * 16 + (lane >> 2)) * TSTR + kk + (lane & 3);
                a[i][0] = Au[ao];
                a[i][1] = Au[ao + 8 * TSTR];
                a[i][2] = Au[ao + 4];
                a[i][3] = Au[ao + 8 * TSTR + 4];
            }
#pragma unroll
            for (int j = 0; j < 8; j++) {
                int bo = (nbase + j * 8 + (lane >> 2)) * TSTR + kk + (lane & 3);
                unsigned b0 = Bu[bo], b1 = Bu[bo + 4];
#pragma unroll
                for (int i = 0; i < 2; i++) {
                    asm volatile(
                        "mma.sync.aligned.m16n8k8.row.col.f32.tf32.tf32.f32 "
                        "{%0,%1,%2,%3}, {%4,%5,%6,%7}, {%8,%9}, {%0,%1,%2,%3};"
                        : "+f"(c[i][j][0]), "+f"(c[i][j][1]),
                          "+f"(c[i][j][2]), "+f"(c[i][j][3])
                        : "r"(a[i][0]), "r"(a[i][1]), "r"(a[i][2]), "r"(a[i][3]),
                          "r"(b0), "r"(b1));
                }
            }
        }
    }

    int crow = lane >> 2, ccol = (lane & 3) * 2;
    const float* rn1 = g_rn[0] + z * Lq;
    const float* rn2 = g_rn[1] + z * Lq;
#pragma unroll
    for (int i = 0; i < 2; i++) {
#pragma unroll
        for (int j = 0; j < 8; j++) {
            int m = m0 + mbase + i * 16 + crow;
            int n = n0 + nbase + j * 8 + ccol;
            float sm0 = rn1[m], sm1 = rn1[m + 8];
            float sn0 = rn2[n], sn1 = rn2[n + 1];
            C[(size_t)m * N + n]           = c[i][j][0] * sm0 * sn0;
            C[(size_t)m * N + n + 1]       = c[i][j][1] * sm0 * sn1;
            C[(size_t)(m + 8) * N + n]     = c[i][j][2] * sm1 * sn0;
            C[(size_t)(m + 8) * N + n + 1] = c[i][j][3] * sm1 * sn1;
        }
    }
}

// ------------------------- persistent GRU scan (bf16 tensor recurrence) -------------------------
#define HSTR 520
#define GRU_SMEM (48 * HSTR * 2 + 32 * HSTR * 2 + 8 * 48 * 33 * 4)

__global__ void __launch_bounds__(256, 1) k_gru(
    const float* __restrict__ whh, const float* __restrict__ bhh,
    const int* __restrict__ len1, const int* __restrict__ len2)
{
    extern __shared__ unsigned short sm16[];
    unsigned short* Ws16 = sm16;                          // [48][HSTR] bf16
    unsigned short* hT16 = sm16 + 48 * HSTR;              // [32][HSTR] bf16
    float* part = (float*)(sm16 + 48 * HSTR + 32 * HSTR); // [8][48*33] fp32

    int chain = blockIdx.x >> 5;
    int blk   = blockIdx.x & 31;
    int side  = chain >> 1, dir = chain & 1;
    int j0    = blk * 16;
    int tid   = threadIdx.x;
    int lane  = tid & 31, warp = tid >> 5;
    const int* lens = side ? len2 : len1;
    const float* gi = g_gi[chain];
    float* enc = g_enc[side];

    for (int i = tid; i < 48 * 512; i += 256) {
        int rr = i >> 9, k = i & 511;
        int g = rr >> 4, u = rr & 15;
        Ws16[rr * HSTR + k] = f2b(whh[((size_t)dir * G3 + g * 512 + j0 + u) * 512 + k]);
    }

    int gb  = tid & 31;
    int u0  = tid >> 5;
    int u1  = u0 + 8;
    int lenb = lens[gb];
    float bhr0 = bhh[dir * G3 +        j0 + u0];
    float bhz0 = bhh[dir * G3 +  512 + j0 + u0];
    float bhn0 = bhh[dir * G3 + 1024 + j0 + u0];
    float bhr1 = bhh[dir * G3 +        j0 + u1];
    float bhz1 = bhh[dir * G3 +  512 + j0 + u1];
    float bhn1 = bhh[dir * G3 + 1024 + j0 + u1];

    int kbase = warp << 6;
    unsigned tgt = 0;
    for (int t = 0; t < Lq; ++t) {
        int p = t & 1;
        const unsigned short* hsrc = g_h[chain][p];
        for (int i = tid; i < 2048; i += 256) {
            uint4 v = __ldcg((const uint4*)(hsrc + i * 8));
            int b = i >> 6, k = (i & 63) * 8;
            *(uint4*)(hT16 + b * HSTR + k) = v;
        }
        __syncthreads();

        size_t tok = (size_t)((gb << 9) | t);
        const float* gp = gi + tok * G3 + j0;
        float ir0 = __ldg(gp + u0), iz0 = __ldg(gp + 512 + u0), in0 = __ldg(gp + 1024 + u0);
        float ir1 = __ldg(gp + u1), iz1 = __ldg(gp + 512 + u1), in1 = __ldg(gp + 1024 + u1);

        float acc[3][4][4];
#pragma unroll
        for (int mt = 0; mt < 3; mt++)
#pragma unroll
            for (int nt = 0; nt < 4; nt++)
#pragma unroll
                for (int r = 0; r < 4; r++) acc[mt][nt][r] = 0.f;

        const unsigned* Wsu = (const unsigned*)Ws16;
        const unsigned* hTu = (const unsigned*)hT16;
#pragma unroll
        for (int ks = 0; ks < 4; ks++) {
            int k0 = kbase + ks * 16;
            int kq = (k0 >> 1) + (lane & 3);
            unsigned a[3][4];
#pragma unroll
            for (int mt = 0; mt < 3; mt++) {
                int ao = (mt * 16 + (lane >> 2)) * 260 + kq;
                a[mt][0] = Wsu[ao];
                a[mt][1] = Wsu[ao + 8 * 260];
                a[mt][2] = Wsu[ao + 4];
                a[mt][3] = Wsu[ao + 8 * 260 + 4];
            }
            unsigned bfr[4][2];
#pragma unroll
            for (int nt = 0; nt < 4; nt++) {
                int bo = (nt * 8 + (lane >> 2)) * 260 + kq;
                bfr[nt][0] = hTu[bo];
                bfr[nt][1] = hTu[bo + 4];
            }
#pragma unroll
            for (int mt = 0; mt < 3; mt++)
#pragma unroll
                for (int nt = 0; nt < 4; nt++) {
                    asm volatile(
                        "mma.sync.aligned.m16n8k16.row.col.f32.bf16.bf16.f32 "
                        "{%0,%1,%2,%3}, {%4,%5,%6,%7}, {%8,%9}, {%0,%1,%2,%3};"
                        : "+f"(acc[mt][nt][0]), "+f"(acc[mt][nt][1]),
                          "+f"(acc[mt][nt][2]), "+f"(acc[mt][nt][3])
                        : "r"(a[mt][0]), "r"(a[mt][1]), "r"(a[mt][2]), "r"(a[mt][3]),
                          "r"(bfr[nt][0]), "r"(bfr[nt][1]));
                }
        }
        {
            float* pw = part + warp * (48 * 33);
            int crow = lane >> 2, ccol = 2 * (lane & 3);
#pragma unroll
            for (int mt = 0; mt < 3; mt++)
#pragma unroll
                for (int nt = 0; nt < 4; nt++) {
                    int r0 = mt * 16 + crow;
                    int c0 = nt * 8 + ccol;
                    pw[r0 * 33 + c0]           = acc[mt][nt][0];
                    pw[r0 * 33 + c0 + 1]       = acc[mt][nt][1];
                    pw[(r0 + 8) * 33 + c0]     = acc[mt][nt][2];
                    pw[(r0 + 8) * 33 + c0 + 1] = acc[mt][nt][3];
                }
        }
        __syncthreads();

        for (int i = tid; i < 1536; i += 256) {
            int rr = i >> 5, b = i & 31;
            float s = 0.f;
#pragma unroll
            for (int w = 0; w < 8; w++) s += part[w * (48 * 33) + rr * 33 + b];
            part[rr * 33 + b] = s;
        }
        __syncthreads();

        bool valid = t < lenb;
        int tout = dir ? (valid ? lenb - 1 - t : t) : t;
        size_t otok = (size_t)((gb << 9) | tout);
        unsigned short* hdst = g_h[chain][p ^ 1];

        float e0, e1;
        {
            unsigned short hpb = hT16[gb * HSTR + j0 + u0];
            float hprev = __bfloat162float(*(__nv_bfloat16*)&hpb);
            float hr = part[u0 * 33 + gb] + bhr0;
            float hz = part[(16 + u0) * 33 + gb] + bhz0;
            float hn = part[(32 + u0) * 33 + gb] + bhn0;
            float r  = 1.f / (1.f + expf(-(ir0 + hr)));
            float zz = 1.f / (1.f + expf(-(iz0 + hz)));
            float nn = tanhf(in0 + r * hn);
            float hnew = (1.f - zz) * nn + zz * hprev;
            hdst[gb * 512 + j0 + u0] = valid ? f2b(hnew) : hpb;
            e0 = valid ? hnew : 0.f;
        }
        {
            unsigned short hpb = hT16[gb * HSTR + j0 + u1];
            float hprev = __bfloat162float(*(__nv_bfloat16*)&hpb);
            float hr = part[u1 * 33 + gb] + bhr1;
            float hz = part[(16 + u1) * 33 + gb] + bhz1;
            float hn = part[(32 + u1) * 33 + gb] + bhn1;
            float r  = 1.f / (1.f + expf(-(ir1 + hr)));
            float zz = 1.f / (1.f + expf(-(iz1 + hz)));
            float nn = tanhf(in1 + r * hn);
            float hnew = (1.f - zz) * nn + zz * hprev;
            hdst[gb * 512 + j0 + u1] = valid ? f2b(hnew) : hpb;
            e1 = valid ? hnew : 0.f;
        }

        __threadfence();
        __syncthreads();
        tgt += 32;
        if (tid == 0) atomicAdd(&g_ctr[chain], 1u);
        enc[otok * 1024 + (dir << 9) + j0 + u0] = e0;
        enc[otok * 1024 + (dir << 9) + j0 + u1] = e1;
        if (tid == 0) {
            while (*(volatile unsigned*)&g_ctr[chain] < tgt) { }
        }
        __syncthreads();
    }
}

// ------------------------- row inverse-norms of enc -------------------------
__global__ void k_norm() {
    const float* row = g_enc[blockIdx.y] + (size_t)blockIdx.x * 1024;
    int tid = threadIdx.x;
    float ss = 0.f;
    for (int i = tid; i < 1024; i += 128) { float v = row[i]; ss += v * v; }
    __shared__ float red[4];
    for (int o = 16; o; o >>= 1) ss += __shfl_down_sync(0xffffffffu, ss, o);
    if ((tid & 31) == 0) red[tid >> 5] = ss;
    __syncthreads();
    if (tid == 0) {
        float tot = red[0] + red[1] + red[2] + red[3];
        g_rn[blockIdx.y][blockIdx.x] = tot > 0.f ? rsqrtf(tot) : 0.f;
    }
}

// ------------------------- row / col max+argmax (first-index ties) -------------------------
__global__ void k_rowmax() {
    int row = blockIdx.x * 8 + (threadIdx.x >> 5);
    int l = threadIdx.x & 31;
    const float* s = g_sim + (size_t)row * Lq;
    float bv = -1e30f; int bi = 0;
    for (int j = l; j < Lq; j += 32) {
        float v = s[j];
        if (v > bv) { bv = v; bi = j; }
    }
    for (int o = 16; o; o >>= 1) {
        float ov = __shfl_down_sync(0xffffffffu, bv, o);
        int   oi = __shfl_down_sync(0xffffffffu, bi, o);
        if (ov > bv || (ov == bv && oi < bi)) { bv = ov; bi = oi; }
    }
    if (l == 0) {
        int i = row & 511;
        g_max1[row] = bv;
        g_rel1[row] = (float)(i - bi);
    }
}

__global__ void k_colmax() {
    int id = blockIdx.x * blockDim.x + threadIdx.x;
    int b = id >> 9, j = id & 511;
    const float* s = g_sim + ((size_t)b * Lq) * Lq + j;
    float bv = -1e30f; int bi = 0;
    for (int i = 0; i < Lq; ++i) {
        float v = s[(size_t)i * Lq];
        if (v > bv) { bv = v; bi = i; }
    }
    g_max2[id] = bv;
    g_rel2[id] = (float)(j - bi);
}

// ------------------------- conv branches + maxpool -------------------------
__global__ void k_head(const float* __restrict__ w2p, const float* __restrict__ w3p,
                       const float* __restrict__ w4p, const float* __restrict__ cb,
                       const float* __restrict__ bg, const float* __restrict__ bb,
                       const float* __restrict__ bm, const float* __restrict__ bvv)
{
    int b = blockIdx.x, br = blockIdx.y;
    __shared__ float x0[512], x1[512];
    const float* ms = br ? g_max2 : g_max1;
    const float* rl = br ? g_rel2 : g_rel1;
    for (int i = threadIdx.x; i < 512; i += 128) {
        x0[i] = ms[b * 512 + i];
        x1[i] = rl[b * 512 + i];
    }
    __syncthreads();
    int c = threadIdx.x;
    float* fout = g_feat + b * 768 + br * 384;
    const float* wp[3] = { w2p, w3p, w4p };
    const int kss[3] = { 2, 3, 4 };
    for (int ki = 0; ki < 3; ++ki) {
        int ks = kss[ki];
        float w0[4], w1[4];
        for (int kk = 0; kk < 4; kk++) {
            w0[kk] = kk < ks ? wp[ki][(c * 2 + 0) * ks + kk] : 0.f;
            w1[kk] = kk < ks ? wp[ki][(c * 2 + 1) * ks + kk] : 0.f;
        }
        float s  = bg[ki * 128 + c] / sqrtf(bvv[ki * 128 + c] + 1e-5f);
        float sh = bb[ki * 128 + c] - bm[ki * 128 + c] * s;
        float bias = cb[ki * 128 + c];
        float best = 0.f;
        for (int p = 0; p <= 512 - ks; ++p) {
            float acc = bias;
#pragma unroll
            for (int kk = 0; kk < 4; kk++)
                if (kk < ks) acc += w0[kk] * x0[p + kk] + w1[kk] * x1[p + kk];
            float y = fmaxf(acc * s + sh, 0.f);
            best = fmaxf(best, y);
        }
        fout[ki * 128 + c] = best;
    }
}

// ------------------------- FC + softmax -------------------------
__global__ void k_fc(const float* __restrict__ fcw, const float* __restrict__ fcb,
                     float* __restrict__ out)
{
    int id = threadIdx.x;
    int b = id >> 1, cls = id & 1;
    float acc = fcb[cls];
    const float* f = g_feat + b * 768;
    const float* wrow = fcw + cls * 768;
    for (int k = 0; k < 768; ++k) acc += f[k] * wrow[k];
    float other = __shfl_xor_sync(0xffffffffu, acc, 1);
    float m = fmaxf(acc, other);
    float e = expf(acc - m);
    float ssum = e + expf(other - m);
    out[id] = e / ssum;
}

// ------------------------- launch -------------------------
extern "C" void kernel_launch(void* const* d_in, const int* in_sizes, int n_in,
                              void* d_out, int out_size)
{
    const int* w1  = (const int*)d_in[0];
    const int* w2  = (const int*)d_in[1];
    const int* p1  = (const int*)d_in[2];
    const int* p2  = (const int*)d_in[3];
    const int* ln1 = (const int*)d_in[4];
    const int* ln2 = (const int*)d_in[5];
    const int* tb1 = (const int*)d_in[6];
    const int* te1 = (const int*)d_in[7];
    const int* tb2 = (const int*)d_in[8];
    const int* te2 = (const int*)d_in[9];
    const float* ew   = (const float*)d_in[10];
    const float* ep   = (const float*)d_in[11];
    const float* pe   = (const float*)d_in[12];
    const float* wih  = (const float*)d_in[13];
    const float* whh  = (const float*)d_in[14];
    const float* bih  = (const float*)d_in[15];
    const float* bhh  = (const float*)d_in[16];
    const float* cw0  = (const float*)d_in[17];
    const float* cw1  = (const float*)d_in[18];
    const float* cw2  = (const float*)d_in[19];
    const float* cb   = (const float*)d_in[20];
    const float* bg   = (const float*)d_in[21];
    const float* bb   = (const float*)d_in[22];
    const float* bm   = (const float*)d_in[23];
    const float* bv   = (const float*)d_in[24];
    const float* fcw  = (const float*)d_in[25];
    const float* fcb  = (const float*)d_in[26];
    float* out = (float*)d_out;

    cudaFuncSetAttribute(k_gemm16, cudaFuncAttributeMaxDynamicSharedMemorySize, G16_SMEM);
    cudaFuncSetAttribute(k_sim, cudaFuncAttributeMaxDynamicSharedMemorySize, SIM_SMEM);
    cudaFuncSetAttribute(k_gru, cudaFuncAttributeMaxDynamicSharedMemorySize, GRU_SMEM);

    k_init<<<512, 256>>>();
    k_cvtw<<<2 * G3 * DIN / 256, 256>>>(wih);
    k_embed<<<dim3(BL, 2), 128>>>(w1, w2, p1, p2, tb1, te1, tb2, te2, ew, ep, pe);
    k_gemm16<<<dim3(G3 / 128, BL / 128, 4), 256, G16_SMEM>>>(bih, ln1, ln2);
    k_gru<<<128, 256, GRU_SMEM>>>(whh, bhh, ln1, ln2);
    k_norm<<<dim3(BL, 2), 128>>>();
    k_sim<<<dim3(Lq / 128, Lq / 128, Bq), 256, SIM_SMEM>>>();
    k_rowmax<<<BL / 8, 256>>>();
    k_colmax<<<BL / 256, 256>>>();
    k_head<<<dim3(Bq, 2), 128>>>(cw0, cw1, cw2, cb, bg, bb, bm, bv);
    k_fc<<<1, 64>>>(fcw, fcb, out);
}

// round 14
// speedup vs baseline: 1.9072x; 1.0060x over previous
#include <cuda_runtime.h>
#include <cuda_bf16.h>
#include <math.h>

#define Bq   32
#define Lq   512
#define Hq   512
#define DIN  832
#define G3   1536
#define BL   (Bq*Lq)          // 16384

// ------------------------- scratch (device globals) -------------------------
__device__ __align__(16) unsigned short g_X[2][(size_t)BL * DIN];   // bf16, 55 MB
__device__ __align__(16) unsigned short g_w16[2 * G3 * DIN];        // bf16 wih copy
__device__ __align__(16) unsigned short g_gi[4][(size_t)BL * G3];   // bf16, 201 MB
__device__ __align__(16) unsigned short g_h[4][2][Bq * Hq];         // bf16 hidden [b][k]
__device__ __align__(16) unsigned short g_enc[2][(size_t)BL * 1024];// bf16, 67 MB
__device__ __align__(16) float g_sim[(size_t)Bq * Lq * Lq];         // 33.5 MB
__device__ __align__(16) float g_rn[2][BL];                         // 1/row-norm of enc
__device__ __align__(16) float g_max1[BL], g_rel1[BL], g_max2[BL], g_rel2[BL];
__device__ __align__(16) float g_feat[Bq * 768];
__device__ unsigned g_ctr[4];

__device__ __forceinline__ void cpa16(void* dst, const void* src) {
    unsigned d = (unsigned)__cvta_generic_to_shared(dst);
    asm volatile("cp.async.cg.shared.global [%0], [%1], 16;\n" :: "r"(d), "l"(src));
}
__device__ __forceinline__ unsigned short f2b(float x) {
    __nv_bfloat16 v = __float2bfloat16(x);
    return *(unsigned short*)&v;
}
__device__ __forceinline__ float b2f(unsigned short u) {
    __nv_bfloat16 v = *(__nv_bfloat16*)&u;
    return __bfloat162float(v);
}

// ------------------------- init -------------------------
__global__ void k_init() {
    int i = blockIdx.x * blockDim.x + threadIdx.x;
    if (i < 4 * 2 * Bq * Hq) (&g_h[0][0][0])[i] = 0;
    if (i < 4) g_ctr[i] = 0u;
}

// ------------------------- wih -> bf16 copy -------------------------
__global__ void k_cvtw(const float* __restrict__ wih) {
    int i = blockIdx.x * 256 + threadIdx.x;
    g_w16[i] = f2b(wih[i]);
}

// ------------------------- embedding concat (bf16 X) -------------------------
__global__ void k_embed(const int* __restrict__ w1, const int* __restrict__ w2,
                        const int* __restrict__ p1, const int* __restrict__ p2,
                        const int* __restrict__ tb1, const int* __restrict__ te1,
                        const int* __restrict__ tb2, const int* __restrict__ te2,
                        const float* __restrict__ ew, const float* __restrict__ ep,
                        const float* __restrict__ pe) {
    int tok  = blockIdx.x;
    int side = blockIdx.y;
    int t    = tok & (Lq - 1);
    const int* w  = side ? w2  : w1;
    const int* pp = side ? p2  : p1;
    const int* tb = side ? tb2 : tb1;
    const int* te = side ? te2 : te1;
    int wi = w[tok], pi = pp[tok], bi = tb[tok], ei = te[tok];
    unsigned short* dst = g_X[side] + (size_t)tok * DIN;
    const float* s0 = ew + (size_t)wi * 256;
    const float* s1 = ep + (size_t)pi * 256;
    for (int i = threadIdx.x; i < 256; i += 128) {
        dst[i]       = f2b(s0[i]);
        dst[256 + i] = f2b(s1[i]);
    }
    const float* q0 = pe + t * 64;
    const float* q1 = pe + bi * 64;
    const float* q2 = pe + ei * 64;
    const float* q3 = pe + (ei - t) * 64;
    const float* q4 = pe + (t - bi) * 64;
    for (int i = threadIdx.x; i < 64; i += 128) {
        dst[512 + i] = f2b(q0[i]);
        dst[576 + i] = f2b(q1[i]);
        dst[640 + i] = f2b(q2[i]);
        dst[704 + i] = f2b(q3[i]);
        dst[768 + i] = f2b(q4[i]);
    }
}

// ------------------------- bf16 gi GEMM (cp.async 3-stage, m16n8k16) -------------------------
// gi[16384,1536](bf16) = X * wih^T + bias, z = side*2+dir, reversed A gather for dir=1.
#define NSTG 3
#define BSTR 20
#define G16_SLOT (2 * 128 * BSTR)
#define G16_SMEM (NSTG * G16_SLOT * 4)

__global__ void __launch_bounds__(256, 2) k_gemm16(
    const float* __restrict__ bih,
    const int* __restrict__ len1, const int* __restrict__ len2)
{
    extern __shared__ unsigned smg[];
    int z = blockIdx.z;
    int side = z >> 1, dir = z & 1;
    const unsigned short* A = g_X[side];
    const unsigned short* B = g_w16 + (size_t)dir * G3 * DIN;
    const float* bias = bih + dir * G3;
    unsigned short* C = g_gi[z];
    const int* lens = side ? len2 : len1;
    int tid = threadIdx.x;
    int m0 = blockIdx.y * 128, n0 = blockIdx.x * 128;

    const unsigned short* asrc[2]; const unsigned short* bsrc[2]; int cdst[2];
#pragma unroll
    for (int i = 0; i < 2; i++) {
        int c = tid + 256 * i;
        int row = c >> 2, q = c & 3;
        int ar = m0 + row;
        if (dir) {
            int b = ar >> 9, t = ar & 511;
            int Lb = lens[b];
            ar = (b << 9) + ((t < Lb) ? (Lb - 1 - t) : t);
        }
        asrc[i] = A + (size_t)ar * DIN + q * 8;
        bsrc[i] = B + (size_t)(n0 + row) * DIN + q * 8;
        cdst[i] = row * BSTR + q * 4;
    }

    const int KT = DIN / 32;
#pragma unroll
    for (int s = 0; s < 2; s++) {
        unsigned* As = smg + s * G16_SLOT;
        unsigned* Bs = As + 128 * BSTR;
#pragma unroll
        for (int i = 0; i < 2; i++) {
            cpa16(As + cdst[i], asrc[i] + s * 32);
            cpa16(Bs + cdst[i], bsrc[i] + s * 32);
        }
        asm volatile("cp.async.commit_group;\n");
    }

    int lane = tid & 31, warp = tid >> 5;
    int mbase = (warp & 3) * 32, nbase = (warp >> 2) * 64;

    float c[2][8][4];
#pragma unroll
    for (int i = 0; i < 2; i++)
#pragma unroll
        for (int j = 0; j < 8; j++)
#pragma unroll
            for (int r = 0; r < 4; r++) c[i][j][r] = 0.f;

    for (int kt = 0; kt < KT; kt++) {
        asm volatile("cp.async.wait_group 1;\n");
        __syncthreads();
        const unsigned* Au = smg + (kt % NSTG) * G16_SLOT;
        const unsigned* Bu = Au + 128 * BSTR;
        if (kt + 2 < KT) {
            unsigned* As2 = smg + ((kt + 2) % NSTG) * G16_SLOT;
            unsigned* Bs2 = As2 + 128 * BSTR;
#pragma unroll
            for (int i = 0; i < 2; i++) {
                cpa16(As2 + cdst[i], asrc[i] + (kt + 2) * 32);
                cpa16(Bs2 + cdst[i], bsrc[i] + (kt + 2) * 32);
            }
        }
        asm volatile("cp.async.commit_group;\n");

#pragma unroll
        for (int ks = 0; ks < 2; ks++) {
            int kw = ks * 8 + (lane & 3);
            unsigned a[2][4];
#pragma unroll
            for (int i = 0; i < 2; i++) {
                int ao = (mbase + i * 16 + (lane >> 2)) * BSTR + kw;
                a[i][0] = Au[ao];
                a[i][1] = Au[ao + 8 * BSTR];
                a[i][2] = Au[ao + 4];
                a[i][3] = Au[ao + 8 * BSTR + 4];
            }
#pragma unroll
            for (int j = 0; j < 8; j++) {
                int bo = (nbase + j * 8 + (lane >> 2)) * BSTR + kw;
                unsigned b0 = Bu[bo], b1 = Bu[bo + 4];
#pragma unroll
                for (int i = 0; i < 2; i++) {
                    asm volatile(
                        "mma.sync.aligned.m16n8k16.row.col.f32.bf16.bf16.f32 "
                        "{%0,%1,%2,%3}, {%4,%5,%6,%7}, {%8,%9}, {%0,%1,%2,%3};"
                        : "+f"(c[i][j][0]), "+f"(c[i][j][1]),
                          "+f"(c[i][j][2]), "+f"(c[i][j][3])
                        : "r"(a[i][0]), "r"(a[i][1]), "r"(a[i][2]), "r"(a[i][3]),
                          "r"(b0), "r"(b1));
                }
            }
        }
    }

    int crow = lane >> 2, ccol = (lane & 3) * 2;
#pragma unroll
    for (int i = 0; i < 2; i++) {
#pragma unroll
        for (int j = 0; j < 8; j++) {
            int m = m0 + mbase + i * 16 + crow;
            int n = n0 + nbase + j * 8 + ccol;
            float b0v = bias[n], b1v = bias[n + 1];
            unsigned p0 = (unsigned)f2b(c[i][j][0] + b0v) | ((unsigned)f2b(c[i][j][1] + b1v) << 16);
            unsigned p1 = (unsigned)f2b(c[i][j][2] + b0v) | ((unsigned)f2b(c[i][j][3] + b1v) << 16);
            *(unsigned*)(C + (size_t)m * G3 + n)       = p0;
            *(unsigned*)(C + (size_t)(m + 8) * G3 + n) = p1;
        }
    }
}

// ------------------------- bf16 sim GEMM + cosine epilogue -------------------------
__global__ void __launch_bounds__(256, 2) k_sim16()
{
    extern __shared__ unsigned smg[];
    int z = blockIdx.z;
    const unsigned short* A = g_enc[0] + (size_t)z * Lq * 1024;
    const unsigned short* B = g_enc[1] + (size_t)z * Lq * 1024;
    float* C = g_sim + (size_t)z * Lq * Lq;
    const int K = 1024, N = Lq;
    int tid = threadIdx.x;
    int m0 = blockIdx.y * 128, n0 = blockIdx.x * 128;

    const unsigned short* asrc[2]; const unsigned short* bsrc[2]; int cdst[2];
#pragma unroll
    for (int i = 0; i < 2; i++) {
        int c = tid + 256 * i;
        int row = c >> 2, q = c & 3;
        asrc[i] = A + (size_t)(m0 + row) * K + q * 8;
        bsrc[i] = B + (size_t)(n0 + row) * K + q * 8;
        cdst[i] = row * BSTR + q * 4;
    }

    const int KT = K / 32;                  // 32
#pragma unroll
    for (int s = 0; s < 2; s++) {
        unsigned* As = smg + s * G16_SLOT;
        unsigned* Bs = As + 128 * BSTR;
#pragma unroll
        for (int i = 0; i < 2; i++) {
            cpa16(As + cdst[i], asrc[i] + s * 32);
            cpa16(Bs + cdst[i], bsrc[i] + s * 32);
        }
        asm volatile("cp.async.commit_group;\n");
    }

    int lane = tid & 31, warp = tid >> 5;
    int mbase = (warp & 3) * 32, nbase = (warp >> 2) * 64;

    float c[2][8][4];
#pragma unroll
    for (int i = 0; i < 2; i++)
#pragma unroll
        for (int j = 0; j < 8; j++)
#pragma unroll
            for (int r = 0; r < 4; r++) c[i][j][r] = 0.f;

    for (int kt = 0; kt < KT; kt++) {
        asm volatile("cp.async.wait_group 1;\n");
        __syncthreads();
        const unsigned* Au = smg + (kt % NSTG) * G16_SLOT;
        const unsigned* Bu = Au + 128 * BSTR;
        if (kt + 2 < KT) {
            unsigned* As2 = smg + ((kt + 2) % NSTG) * G16_SLOT;
            unsigned* Bs2 = As2 + 128 * BSTR;
#pragma unroll
            for (int i = 0; i < 2; i++) {
                cpa16(As2 + cdst[i], asrc[i] + (kt + 2) * 32);
                cpa16(Bs2 + cdst[i], bsrc[i] + (kt + 2) * 32);
            }
        }
        asm volatile("cp.async.commit_group;\n");

#pragma unroll
        for (int ks = 0; ks < 2; ks++) {
            int kw = ks * 8 + (lane & 3);
            unsigned a[2][4];
#pragma unroll
            for (int i = 0; i < 2; i++) {
                int ao = (mbase + i * 16 + (lane >> 2)) * BSTR + kw;
                a[i][0] = Au[ao];
                a[i][1] = Au[ao + 8 * BSTR];
                a[i][2] = Au[ao + 4];
                a[i][3] = Au[ao + 8 * BSTR + 4];
            }
#pragma unroll
            for (int j = 0; j < 8; j++) {
                int bo = (nbase + j * 8 + (lane >> 2)) * BSTR + kw;
                unsigned b0 = Bu[bo], b1 = Bu[bo + 4];
#pragma unroll
                for (int i = 0; i < 2; i++) {
                    asm volatile(
                        "mma.sync.aligned.m16n8k16.row.col.f32.bf16.bf16.f32 "
                        "{%0,%1,%2,%3}, {%4,%5,%6,%7}, {%8,%9}, {%0,%1,%2,%3};"
                        : "+f"(c[i][j][0]), "+f"(c[i][j][1]),
                          "+f"(c[i][j][2]), "+f"(c[i][j][3])
                        : "r"(a[i][0]), "r"(a[i][1]), "r"(a[i][2]), "r"(a[i][3]),
                          "r"(b0), "r"(b1));
                }
            }
        }
    }

    int crow = lane >> 2, ccol = (lane & 3) * 2;
    const float* rn1 = g_rn[0] + z * Lq;
    const float* rn2 = g_rn[1] + z * Lq;
#pragma unroll
    for (int i = 0; i < 2; i++) {
#pragma unroll
        for (int j = 0; j < 8; j++) {
            int m = m0 + mbase + i * 16 + crow;
            int n = n0 + nbase + j * 8 + ccol;
            float sm0 = rn1[m], sm1 = rn1[m + 8];
            float sn0 = rn2[n], sn1 = rn2[n + 1];
            C[(size_t)m * N + n]           = c[i][j][0] * sm0 * sn0;
            C[(size_t)m * N + n + 1]       = c[i][j][1] * sm0 * sn1;
            C[(size_t)(m + 8) * N + n]     = c[i][j][2] * sm1 * sn0;
            C[(size_t)(m + 8) * N + n + 1] = c[i][j][3] * sm1 * sn1;
        }
    }
}

// ------------------------- persistent GRU scan (bf16 tensor recurrence) -------------------------
#define HSTR 520
#define GRU_SMEM (48 * HSTR * 2 + 32 * HSTR * 2 + 8 * 48 * 33 * 4)

__global__ void __launch_bounds__(256, 1) k_gru(
    const float* __restrict__ whh, const float* __restrict__ bhh,
    const int* __restrict__ len1, const int* __restrict__ len2)
{
    extern __shared__ unsigned short sm16[];
    unsigned short* Ws16 = sm16;                          // [48][HSTR] bf16
    unsigned short* hT16 = sm16 + 48 * HSTR;              // [32][HSTR] bf16
    float* part = (float*)(sm16 + 48 * HSTR + 32 * HSTR); // [8][48*33] fp32

    int chain = blockIdx.x >> 5;
    int blk   = blockIdx.x & 31;
    int side  = chain >> 1, dir = chain & 1;
    int j0    = blk * 16;
    int tid   = threadIdx.x;
    int lane  = tid & 31, warp = tid >> 5;
    const int* lens = side ? len2 : len1;
    const unsigned short* gi = g_gi[chain];
    unsigned short* enc = g_enc[side];

    for (int i = tid; i < 48 * 512; i += 256) {
        int rr = i >> 9, k = i & 511;
        int g = rr >> 4, u = rr & 15;
        Ws16[rr * HSTR + k] = f2b(whh[((size_t)dir * G3 + g * 512 + j0 + u) * 512 + k]);
    }

    int gb  = tid & 31;
    int u0  = tid >> 5;
    int u1  = u0 + 8;
    int lenb = lens[gb];
    float bhr0 = bhh[dir * G3 +        j0 + u0];
    float bhz0 = bhh[dir * G3 +  512 + j0 + u0];
    float bhn0 = bhh[dir * G3 + 1024 + j0 + u0];
    float bhr1 = bhh[dir * G3 +        j0 + u1];
    float bhz1 = bhh[dir * G3 +  512 + j0 + u1];
    float bhn1 = bhh[dir * G3 + 1024 + j0 + u1];

    int kbase = warp << 6;
    unsigned tgt = 0;
    for (int t = 0; t < Lq; ++t) {
        int p = t & 1;
        const unsigned short* hsrc = g_h[chain][p];
        for (int i = tid; i < 2048; i += 256) {
            uint4 v = __ldcg((const uint4*)(hsrc + i * 8));
            int b = i >> 6, k = (i & 63) * 8;
            *(uint4*)(hT16 + b * HSTR + k) = v;
        }
        __syncthreads();

        size_t tok = (size_t)((gb << 9) | t);
        const unsigned short* gp = gi + tok * G3 + j0;
        float ir0 = b2f(__ldg(gp + u0)), iz0 = b2f(__ldg(gp + 512 + u0)), in0 = b2f(__ldg(gp + 1024 + u0));
        float ir1 = b2f(__ldg(gp + u1)), iz1 = b2f(__ldg(gp + 512 + u1)), in1 = b2f(__ldg(gp + 1024 + u1));

        float acc[3][4][4];
#pragma unroll
        for (int mt = 0; mt < 3; mt++)
#pragma unroll
            for (int nt = 0; nt < 4; nt++)
#pragma unroll
                for (int r = 0; r < 4; r++) acc[mt][nt][r] = 0.f;

        const unsigned* Wsu = (const unsigned*)Ws16;
        const unsigned* hTu = (const unsigned*)hT16;
#pragma unroll
        for (int ks = 0; ks < 4; ks++) {
            int k0 = kbase + ks * 16;
            int kq = (k0 >> 1) + (lane & 3);
            unsigned a[3][4];
#pragma unroll
            for (int mt = 0; mt < 3; mt++) {
                int ao = (mt * 16 + (lane >> 2)) * 260 + kq;
                a[mt][0] = Wsu[ao];
                a[mt][1] = Wsu[ao + 8 * 260];
                a[mt][2] = Wsu[ao + 4];
                a[mt][3] = Wsu[ao + 8 * 260 + 4];
            }
            unsigned bfr[4][2];
#pragma unroll
            for (int nt = 0; nt < 4; nt++) {
                int bo = (nt * 8 + (lane >> 2)) * 260 + kq;
                bfr[nt][0] = hTu[bo];
                bfr[nt][1] = hTu[bo + 4];
            }
#pragma unroll
            for (int mt = 0; mt < 3; mt++)
#pragma unroll
                for (int nt = 0; nt < 4; nt++) {
                    asm volatile(
                        "mma.sync.aligned.m16n8k16.row.col.f32.bf16.bf16.f32 "
                        "{%0,%1,%2,%3}, {%4,%5,%6,%7}, {%8,%9}, {%0,%1,%2,%3};"
                        : "+f"(acc[mt][nt][0]), "+f"(acc[mt][nt][1]),
                          "+f"(acc[mt][nt][2]), "+f"(acc[mt][nt][3])
                        : "r"(a[mt][0]), "r"(a[mt][1]), "r"(a[mt][2]), "r"(a[mt][3]),
                          "r"(bfr[nt][0]), "r"(bfr[nt][1]));
                }
        }
        {
            float* pw = part + warp * (48 * 33);
            int crow = lane >> 2, ccol = 2 * (lane & 3);
#pragma unroll
            for (int mt = 0; mt < 3; mt++)
#pragma unroll
                for (int nt = 0; nt < 4; nt++) {
                    int r0 = mt * 16 + crow;
                    int c0 = nt * 8 + ccol;
                    pw[r0 * 33 + c0]           = acc[mt][nt][0];
                    pw[r0 * 33 + c0 + 1]       = acc[mt][nt][1];
                    pw[(r0 + 8) * 33 + c0]     = acc[mt][nt][2];
                    pw[(r0 + 8) * 33 + c0 + 1] = acc[mt][nt][3];
                }
        }
        __syncthreads();

        for (int i = tid; i < 1536; i += 256) {
            int rr = i >> 5, b = i & 31;
            float s = 0.f;
#pragma unroll
            for (int w = 0; w < 8; w++) s += part[w * (48 * 33) + rr * 33 + b];
            part[rr * 33 + b] = s;
        }
        __syncthreads();

        bool valid = t < lenb;
        int tout = dir ? (valid ? lenb - 1 - t : t) : t;
        size_t otok = (size_t)((gb << 9) | tout);
        unsigned short* hdst = g_h[chain][p ^ 1];

        unsigned short e0, e1;
        {
            unsigned short hpb = hT16[gb * HSTR + j0 + u0];
            float hprev = b2f(hpb);
            float hr = part[u0 * 33 + gb] + bhr0;
            float hz = part[(16 + u0) * 33 + gb] + bhz0;
            float hn = part[(32 + u0) * 33 + gb] + bhn0;
            float r  = 1.f / (1.f + expf(-(ir0 + hr)));
            float zz = 1.f / (1.f + expf(-(iz0 + hz)));
            float nn = tanhf(in0 + r * hn);
            float hnew = (1.f - zz) * nn + zz * hprev;
            unsigned short hb = f2b(hnew);
            hdst[gb * 512 + j0 + u0] = valid ? hb : hpb;
            e0 = valid ? hb : 0;
        }
        {
            unsigned short hpb = hT16[gb * HSTR + j0 + u1];
            float hprev = b2f(hpb);
            float hr = part[u1 * 33 + gb] + bhr1;
            float hz = part[(16 + u1) * 33 + gb] + bhz1;
            float hn = part[(32 + u1) * 33 + gb] + bhn1;
            float r  = 1.f / (1.f + expf(-(ir1 + hr)));
            float zz = 1.f / (1.f + expf(-(iz1 + hz)));
            float nn = tanhf(in1 + r * hn);
            float hnew = (1.f - zz) * nn + zz * hprev;
            unsigned short hb = f2b(hnew);
            hdst[gb * 512 + j0 + u1] = valid ? hb : hpb;
            e1 = valid ? hb : 0;
        }

        __threadfence();
        __syncthreads();
        tgt += 32;
        if (tid == 0) atomicAdd(&g_ctr[chain], 1u);
        enc[otok * 1024 + (dir << 9) + j0 + u0] = e0;
        enc[otok * 1024 + (dir << 9) + j0 + u1] = e1;
        if (tid == 0) {
            while (*(volatile unsigned*)&g_ctr[chain] < tgt) { }
        }
        __syncthreads();
    }
}

// ------------------------- row inverse-norms of enc (bf16 input) -------------------------
__global__ void k_norm() {
    const unsigned short* row = g_enc[blockIdx.y] + (size_t)blockIdx.x * 1024;
    int tid = threadIdx.x;
    uint4 v = ((const uint4*)row)[tid];          // 8 bf16 per thread
    float ss = 0.f;
    unsigned ws[4] = { v.x, v.y, v.z, v.w };
#pragma unroll
    for (int i = 0; i < 4; i++) {
        float a = b2f((unsigned short)(ws[i] & 0xffff));
        float b = b2f((unsigned short)(ws[i] >> 16));
        ss += a * a + b * b;
    }
    __shared__ float red[4];
    for (int o = 16; o; o >>= 1) ss += __shfl_down_sync(0xffffffffu, ss, o);
    if ((tid & 31) == 0) red[tid >> 5] = ss;
    __syncthreads();
    if (tid == 0) {
        float tot = red[0] + red[1] + red[2] + red[3];
        g_rn[blockIdx.y][blockIdx.x] = tot > 0.f ? rsqrtf(tot) : 0.f;
    }
}

// ------------------------- row / col max+argmax (first-index ties) -------------------------
__global__ void k_rowmax() {
    int row = blockIdx.x * 8 + (threadIdx.x >> 5);
    int l = threadIdx.x & 31;
    const float* s = g_sim + (size_t)row * Lq;
    float bv = -1e30f; int bi = 0;
    for (int j = l; j < Lq; j += 32) {
        float v = s[j];
        if (v > bv) { bv = v; bi = j; }
    }
    for (int o = 16; o; o >>= 1) {
        float ov = __shfl_down_sync(0xffffffffu, bv, o);
        int   oi = __shfl_down_sync(0xffffffffu, bi, o);
        if (ov > bv || (ov == bv && oi < bi)) { bv = ov; bi = oi; }
    }
    if (l == 0) {
        int i = row & 511;
        g_max1[row] = bv;
        g_rel1[row] = (float)(i - bi);
    }
}

__global__ void k_colmax() {
    int id = blockIdx.x * blockDim.x + threadIdx.x;
    int b = id >> 9, j = id & 511;
    const float* s = g_sim + ((size_t)b * Lq) * Lq + j;
    float bv = -1e30f; int bi = 0;
    for (int i = 0; i < Lq; ++i) {
        float v = s[(size_t)i * Lq];
        if (v > bv) { bv = v; bi = i; }
    }
    g_max2[id] = bv;
    g_rel2[id] = (float)(j - bi);
}

// ------------------------- conv branches + maxpool -------------------------
__global__ void k_head(const float* __restrict__ w2p, const float* __restrict__ w3p,
                       const float* __restrict__ w4p, const float* __restrict__ cb,
                       const float* __restrict__ bg, const float* __restrict__ bb,
                       const float* __restrict__ bm, const float* __restrict__ bvv)
{
    int b = blockIdx.x, br = blockIdx.y;
    __shared__ float x0[512], x1[512];
    const float* ms = br ? g_max2 : g_max1;
    const float* rl = br ? g_rel2 : g_rel1;
    for (int i = threadIdx.x; i < 512; i += 128) {
        x0[i] = ms[b * 512 + i];
        x1[i] = rl[b * 512 + i];
    }
    __syncthreads();
    int c = threadIdx.x;
    float* fout = g_feat + b * 768 + br * 384;
    const float* wp[3] = { w2p, w3p, w4p };
    const int kss[3] = { 2, 3, 4 };
    for (int ki = 0; ki < 3; ++ki) {
        int ks = kss[ki];
        float w0[4], w1[4];
        for (int kk = 0; kk < 4; kk++) {
            w0[kk] = kk < ks ? wp[ki][(c * 2 + 0) * ks + kk] : 0.f;
            w1[kk] = kk < ks ? wp[ki][(c * 2 + 1) * ks + kk] : 0.f;
        }
        float s  = bg[ki * 128 + c] / sqrtf(bvv[ki * 128 + c] + 1e-5f);
        float sh = bb[ki * 128 + c] - bm[ki * 128 + c] * s;
        float bias = cb[ki * 128 + c];
        float best = 0.f;
        for (int p = 0; p <= 512 - ks; ++p) {
            float acc = bias;
#pragma unroll
            for (int kk = 0; kk < 4; kk++)
                if (kk < ks) acc += w0[kk] * x0[p + kk] + w1[kk] * x1[p + kk];
            float y = fmaxf(acc * s + sh, 0.f);
            best = fmaxf(best, y);
        }
        fout[ki * 128 + c] = best;
    }
}

// ------------------------- FC + softmax -------------------------
__global__ void k_fc(const float* __restrict__ fcw, const float* __restrict__ fcb,
                     float* __restrict__ out)
{
    int id = threadIdx.x;
    int b = id >> 1, cls = id & 1;
    float acc = fcb[cls];
    const float* f = g_feat + b * 768;
    const float* wrow = fcw + cls * 768;
    for (int k = 0; k < 768; ++k) acc += f[k] * wrow[k];
    float other = __shfl_xor_sync(0xffffffffu, acc, 1);
    float m = fmaxf(acc, other);
    float e = expf(acc - m);
    float ssum = e + expf(other - m);
    out[id] = e / ssum;
}

// ------------------------- launch -------------------------
extern "C" void kernel_launch(void* const* d_in, const int* in_sizes, int n_in,
                              void* d_out, int out_size)
{
    const int* w1  = (const int*)d_in[0];
    const int* w2  = (const int*)d_in[1];
    const int* p1  = (const int*)d_in[2];
    const int* p2  = (const int*)d_in[3];
    const int* ln1 = (const int*)d_in[4];
    const int* ln2 = (const int*)d_in[5];
    const int* tb1 = (const int*)d_in[6];
    const int* te1 = (const int*)d_in[7];
    const int* tb2 = (const int*)d_in[8];
    const int* te2 = (const int*)d_in[9];
    const float* ew   = (const float*)d_in[10];
    const float* ep   = (const float*)d_in[11];
    const float* pe   = (const float*)d_in[12];
    const float* wih  = (const float*)d_in[13];
    const float* whh  = (const float*)d_in[14];
    const float* bih  = (const float*)d_in[15];
    const float* bhh  = (const float*)d_in[16];
    const float* cw0  = (const float*)d_in[17];
    const float* cw1  = (const float*)d_in[18];
    const float* cw2  = (const float*)d_in[19];
    const float* cb   = (const float*)d_in[20];
    const float* bg   = (const float*)d_in[21];
    const float* bb   = (const float*)d_in[22];
    const float* bm   = (const float*)d_in[23];
    const float* bv   = (const float*)d_in[24];
    const float* fcw  = (const float*)d_in[25];
    const float* fcb  = (const float*)d_in[26];
    float* out = (float*)d_out;

    cudaFuncSetAttribute(k_gemm16, cudaFuncAttributeMaxDynamicSharedMemorySize, G16_SMEM);
    cudaFuncSetAttribute(k_sim16, cudaFuncAttributeMaxDynamicSharedMemorySize, G16_SMEM);
    cudaFuncSetAttribute(k_gru, cudaFuncAttributeMaxDynamicSharedMemorySize, GRU_SMEM);

    k_init<<<512, 256>>>();
    k_cvtw<<<2 * G3 * DIN / 256, 256>>>(wih);
    k_embed<<<dim3(BL, 2), 128>>>(w1, w2, p1, p2, tb1, te1, tb2, te2, ew, ep, pe);
    k_gemm16<<<dim3(G3 / 128, BL / 128, 4), 256, G16_SMEM>>>(bih, ln1, ln2);
    k_gru<<<128, 256, GRU_SMEM>>>(whh, bhh, ln1, ln2);
    k_norm<<<dim3(BL, 2), 128>>>();
    k_sim16<<<dim3(Lq / 128, Lq / 128, Bq), 256, G16_SMEM>>>();
    k_rowmax<<<BL / 8, 256>>>();
    k_colmax<<<BL / 256, 256>>>();
    k_head<<<dim3(Bq, 2), 128>>>(cw0, cw1, cw2, cb, bg, bb, bm, bv);
    k_fc<<<1, 64>>>(fcw, fcb, out);
}

// round 15
// speedup vs baseline: 1.9644x; 1.0300x over previous
#include <cuda_runtime.h>
#include <cuda_bf16.h>
#include <math.h>

#define Bq   32
#define Lq   512
#define Hq   512
#define DIN  832
#define G3   1536
#define BL   (Bq*Lq)          // 16384

// ------------------------- scratch (device globals) -------------------------
__device__ __align__(16) unsigned short g_X[2][(size_t)BL * DIN];   // bf16, 55 MB
__device__ __align__(16) unsigned short g_w16[2 * G3 * DIN];        // bf16 wih copy
__device__ __align__(16) unsigned short g_gi[4][(size_t)BL * G3];   // bf16, 201 MB
__device__ __align__(16) unsigned short g_h[4][2][Bq * Hq];         // bf16 hidden [b][k]
__device__ __align__(16) unsigned short g_enc[2][(size_t)BL * 1024];// bf16, 67 MB
__device__ __align__(16) float g_sim[(size_t)Bq * Lq * Lq];         // 33.5 MB
__device__ __align__(16) float g_rn[2][BL];                         // 1/row-norm of enc
__device__ __align__(16) float g_max1[BL], g_rel1[BL], g_max2[BL], g_rel2[BL];
__device__ __align__(16) float g_feat[Bq * 768];
__device__ unsigned g_ctr[4];

__device__ __forceinline__ void cpa16(void* dst, const void* src) {
    unsigned d = (unsigned)__cvta_generic_to_shared(dst);
    asm volatile("cp.async.cg.shared.global [%0], [%1], 16;\n" :: "r"(d), "l"(src));
}
__device__ __forceinline__ unsigned short f2b(float x) {
    __nv_bfloat16 v = __float2bfloat16(x);
    return *(unsigned short*)&v;
}
__device__ __forceinline__ float b2f(unsigned short u) {
    __nv_bfloat16 v = *(__nv_bfloat16*)&u;
    return __bfloat162float(v);
}

// ------------------------- init -------------------------
__global__ void k_init() {
    int i = blockIdx.x * blockDim.x + threadIdx.x;
    if (i < 4 * 2 * Bq * Hq) (&g_h[0][0][0])[i] = 0;
    if (i < 4) g_ctr[i] = 0u;
}

// ------------------------- wih -> bf16 copy -------------------------
__global__ void k_cvtw(const float* __restrict__ wih) {
    int i = blockIdx.x * 256 + threadIdx.x;
    g_w16[i] = f2b(wih[i]);
}

// ------------------------- embedding concat (bf16 X) -------------------------
__global__ void k_embed(const int* __restrict__ w1, const int* __restrict__ w2,
                        const int* __restrict__ p1, const int* __restrict__ p2,
                        const int* __restrict__ tb1, const int* __restrict__ te1,
                        const int* __restrict__ tb2, const int* __restrict__ te2,
                        const float* __restrict__ ew, const float* __restrict__ ep,
                        const float* __restrict__ pe) {
    int tok  = blockIdx.x;
    int side = blockIdx.y;
    int t    = tok & (Lq - 1);
    const int* w  = side ? w2  : w1;
    const int* pp = side ? p2  : p1;
    const int* tb = side ? tb2 : tb1;
    const int* te = side ? te2 : te1;
    int wi = w[tok], pi = pp[tok], bi = tb[tok], ei = te[tok];
    unsigned short* dst = g_X[side] + (size_t)tok * DIN;
    const float* s0 = ew + (size_t)wi * 256;
    const float* s1 = ep + (size_t)pi * 256;
    for (int i = threadIdx.x; i < 256; i += 128) {
        dst[i]       = f2b(s0[i]);
        dst[256 + i] = f2b(s1[i]);
    }
    const float* q0 = pe + t * 64;
    const float* q1 = pe + bi * 64;
    const float* q2 = pe + ei * 64;
    const float* q3 = pe + (ei - t) * 64;
    const float* q4 = pe + (t - bi) * 64;
    for (int i = threadIdx.x; i < 64; i += 128) {
        dst[512 + i] = f2b(q0[i]);
        dst[576 + i] = f2b(q1[i]);
        dst[640 + i] = f2b(q2[i]);
        dst[704 + i] = f2b(q3[i]);
        dst[768 + i] = f2b(q4[i]);
    }
}

// ------------------------- bf16 gi GEMM (cp.async 3-stage, m16n8k16) -------------------------
#define NSTG 3
#define BSTR 20
#define G16_SLOT (2 * 128 * BSTR)
#define G16_SMEM (NSTG * G16_SLOT * 4)

__global__ void __launch_bounds__(256, 2) k_gemm16(
    const float* __restrict__ bih,
    const int* __restrict__ len1, const int* __restrict__ len2)
{
    extern __shared__ unsigned smg[];
    int z = blockIdx.z;
    int side = z >> 1, dir = z & 1;
    const unsigned short* A = g_X[side];
    const unsigned short* B = g_w16 + (size_t)dir * G3 * DIN;
    const float* bias = bih + dir * G3;
    unsigned short* C = g_gi[z];
    const int* lens = side ? len2 : len1;
    int tid = threadIdx.x;
    int m0 = blockIdx.y * 128, n0 = blockIdx.x * 128;

    const unsigned short* asrc[2]; const unsigned short* bsrc[2]; int cdst[2];
#pragma unroll
    for (int i = 0; i < 2; i++) {
        int c = tid + 256 * i;
        int row = c >> 2, q = c & 3;
        int ar = m0 + row;
        if (dir) {
            int b = ar >> 9, t = ar & 511;
            int Lb = lens[b];
            ar = (b << 9) + ((t < Lb) ? (Lb - 1 - t) : t);
        }
        asrc[i] = A + (size_t)ar * DIN + q * 8;
        bsrc[i] = B + (size_t)(n0 + row) * DIN + q * 8;
        cdst[i] = row * BSTR + q * 4;
    }

    const int KT = DIN / 32;
#pragma unroll
    for (int s = 0; s < 2; s++) {
        unsigned* As = smg + s * G16_SLOT;
        unsigned* Bs = As + 128 * BSTR;
#pragma unroll
        for (int i = 0; i < 2; i++) {
            cpa16(As + cdst[i], asrc[i] + s * 32);
            cpa16(Bs + cdst[i], bsrc[i] + s * 32);
        }
        asm volatile("cp.async.commit_group;\n");
    }

    int lane = tid & 31, warp = tid >> 5;
    int mbase = (warp & 3) * 32, nbase = (warp >> 2) * 64;

    float c[2][8][4];
#pragma unroll
    for (int i = 0; i < 2; i++)
#pragma unroll
        for (int j = 0; j < 8; j++)
#pragma unroll
            for (int r = 0; r < 4; r++) c[i][j][r] = 0.f;

    for (int kt = 0; kt < KT; kt++) {
        asm volatile("cp.async.wait_group 1;\n");
        __syncthreads();
        const unsigned* Au = smg + (kt % NSTG) * G16_SLOT;
        const unsigned* Bu = Au + 128 * BSTR;
        if (kt + 2 < KT) {
            unsigned* As2 = smg + ((kt + 2) % NSTG) * G16_SLOT;
            unsigned* Bs2 = As2 + 128 * BSTR;
#pragma unroll
            for (int i = 0; i < 2; i++) {
                cpa16(As2 + cdst[i], asrc[i] + (kt + 2) * 32);
                cpa16(Bs2 + cdst[i], bsrc[i] + (kt + 2) * 32);
            }
        }
        asm volatile("cp.async.commit_group;\n");

#pragma unroll
        for (int ks = 0; ks < 2; ks++) {
            int kw = ks * 8 + (lane & 3);
            unsigned a[2][4];
#pragma unroll
            for (int i = 0; i < 2; i++) {
                int ao = (mbase + i * 16 + (lane >> 2)) * BSTR + kw;
                a[i][0] = Au[ao];
                a[i][1] = Au[ao + 8 * BSTR];
                a[i][2] = Au[ao + 4];
                a[i][3] = Au[ao + 8 * BSTR + 4];
            }
#pragma unroll
            for (int j = 0; j < 8; j++) {
                int bo = (nbase + j * 8 + (lane >> 2)) * BSTR + kw;
                unsigned b0 = Bu[bo], b1 = Bu[bo + 4];
#pragma unroll
                for (int i = 0; i < 2; i++) {
                    asm volatile(
                        "mma.sync.aligned.m16n8k16.row.col.f32.bf16.bf16.f32 "
                        "{%0,%1,%2,%3}, {%4,%5,%6,%7}, {%8,%9}, {%0,%1,%2,%3};"
                        : "+f"(c[i][j][0]), "+f"(c[i][j][1]),
                          "+f"(c[i][j][2]), "+f"(c[i][j][3])
                        : "r"(a[i][0]), "r"(a[i][1]), "r"(a[i][2]), "r"(a[i][3]),
                          "r"(b0), "r"(b1));
                }
            }
        }
    }

    int crow = lane >> 2, ccol = (lane & 3) * 2;
#pragma unroll
    for (int i = 0; i < 2; i++) {
#pragma unroll
        for (int j = 0; j < 8; j++) {
            int m = m0 + mbase + i * 16 + crow;
            int n = n0 + nbase + j * 8 + ccol;
            float b0v = bias[n], b1v = bias[n + 1];
            unsigned p0 = (unsigned)f2b(c[i][j][0] + b0v) | ((unsigned)f2b(c[i][j][1] + b1v) << 16);
            unsigned p1 = (unsigned)f2b(c[i][j][2] + b0v) | ((unsigned)f2b(c[i][j][3] + b1v) << 16);
            *(unsigned*)(C + (size_t)m * G3 + n)       = p0;
            *(unsigned*)(C + (size_t)(m + 8) * G3 + n) = p1;
        }
    }
}

// ------------------------- bf16 sim GEMM + cosine epilogue -------------------------
__global__ void __launch_bounds__(256, 2) k_sim16()
{
    extern __shared__ unsigned smg[];
    int z = blockIdx.z;
    const unsigned short* A = g_enc[0] + (size_t)z * Lq * 1024;
    const unsigned short* B = g_enc[1] + (size_t)z * Lq * 1024;
    float* C = g_sim + (size_t)z * Lq * Lq;
    const int K = 1024, N = Lq;
    int tid = threadIdx.x;
    int m0 = blockIdx.y * 128, n0 = blockIdx.x * 128;

    const unsigned short* asrc[2]; const unsigned short* bsrc[2]; int cdst[2];
#pragma unroll
    for (int i = 0; i < 2; i++) {
        int c = tid + 256 * i;
        int row = c >> 2, q = c & 3;
        asrc[i] = A + (size_t)(m0 + row) * K + q * 8;
        bsrc[i] = B + (size_t)(n0 + row) * K + q * 8;
        cdst[i] = row * BSTR + q * 4;
    }

    const int KT = K / 32;
#pragma unroll
    for (int s = 0; s < 2; s++) {
        unsigned* As = smg + s * G16_SLOT;
        unsigned* Bs = As + 128 * BSTR;
#pragma unroll
        for (int i = 0; i < 2; i++) {
            cpa16(As + cdst[i], asrc[i] + s * 32);
            cpa16(Bs + cdst[i], bsrc[i] + s * 32);
        }
        asm volatile("cp.async.commit_group;\n");
    }

    int lane = tid & 31, warp = tid >> 5;
    int mbase = (warp & 3) * 32, nbase = (warp >> 2) * 64;

    float c[2][8][4];
#pragma unroll
    for (int i = 0; i < 2; i++)
#pragma unroll
        for (int j = 0; j < 8; j++)
#pragma unroll
            for (int r = 0; r < 4; r++) c[i][j][r] = 0.f;

    for (int kt = 0; kt < KT; kt++) {
        asm volatile("cp.async.wait_group 1;\n");
        __syncthreads();
        const unsigned* Au = smg + (kt % NSTG) * G16_SLOT;
        const unsigned* Bu = Au + 128 * BSTR;
        if (kt + 2 < KT) {
            unsigned* As2 = smg + ((kt + 2) % NSTG) * G16_SLOT;
            unsigned* Bs2 = As2 + 128 * BSTR;
#pragma unroll
            for (int i = 0; i < 2; i++) {
                cpa16(As2 + cdst[i], asrc[i] + (kt + 2) * 32);
                cpa16(Bs2 + cdst[i], bsrc[i] + (kt + 2) * 32);
            }
        }
        asm volatile("cp.async.commit_group;\n");

#pragma unroll
        for (int ks = 0; ks < 2; ks++) {
            int kw = ks * 8 + (lane & 3);
            unsigned a[2][4];
#pragma unroll
            for (int i = 0; i < 2; i++) {
                int ao = (mbase + i * 16 + (lane >> 2)) * BSTR + kw;
                a[i][0] = Au[ao];
                a[i][1] = Au[ao + 8 * BSTR];
                a[i][2] = Au[ao + 4];
                a[i][3] = Au[ao + 8 * BSTR + 4];
            }
#pragma unroll
            for (int j = 0; j < 8; j++) {
                int bo = (nbase + j * 8 + (lane >> 2)) * BSTR + kw;
                unsigned b0 = Bu[bo], b1 = Bu[bo + 4];
#pragma unroll
                for (int i = 0; i < 2; i++) {
                    asm volatile(
                        "mma.sync.aligned.m16n8k16.row.col.f32.bf16.bf16.f32 "
                        "{%0,%1,%2,%3}, {%4,%5,%6,%7}, {%8,%9}, {%0,%1,%2,%3};"
                        : "+f"(c[i][j][0]), "+f"(c[i][j][1]),
                          "+f"(c[i][j][2]), "+f"(c[i][j][3])
                        : "r"(a[i][0]), "r"(a[i][1]), "r"(a[i][2]), "r"(a[i][3]),
                          "r"(b0), "r"(b1));
                }
            }
        }
    }

    int crow = lane >> 2, ccol = (lane & 3) * 2;
    const float* rn1 = g_rn[0] + z * Lq;
    const float* rn2 = g_rn[1] + z * Lq;
#pragma unroll
    for (int i = 0; i < 2; i++) {
#pragma unroll
        for (int j = 0; j < 8; j++) {
            int m = m0 + mbase + i * 16 + crow;
            int n = n0 + nbase + j * 8 + ccol;
            float sm0 = rn1[m], sm1 = rn1[m + 8];
            float sn0 = rn2[n], sn1 = rn2[n + 1];
            C[(size_t)m * N + n]           = c[i][j][0] * sm0 * sn0;
            C[(size_t)m * N + n + 1]       = c[i][j][1] * sm0 * sn1;
            C[(size_t)(m + 8) * N + n]     = c[i][j][2] * sm1 * sn0;
            C[(size_t)(m + 8) * N + n + 1] = c[i][j][3] * sm1 * sn1;
        }
    }
}

// ------------------------- persistent GRU scan (bf16 tensor recurrence) -------------------------
// gi gate values loaded COALESCED into smem gis[48][33] (fixes 16x sector overfetch).
#define HSTR 520
#define GRU_SMEM (48 * HSTR * 2 + 32 * HSTR * 2 + 8 * 48 * 33 * 4 + 48 * 33 * 2 + 32)

__global__ void __launch_bounds__(256, 1) k_gru(
    const float* __restrict__ whh, const float* __restrict__ bhh,
    const int* __restrict__ len1, const int* __restrict__ len2)
{
    extern __shared__ unsigned short sm16[];
    unsigned short* Ws16 = sm16;                          // [48][HSTR] bf16
    unsigned short* hT16 = sm16 + 48 * HSTR;              // [32][HSTR] bf16
    float* part = (float*)(sm16 + 48 * HSTR + 32 * HSTR); // [8][48*33] fp32
    unsigned short* gis = (unsigned short*)(part + 8 * 48 * 33); // [48][33] bf16 gate vals

    int chain = blockIdx.x >> 5;
    int blk   = blockIdx.x & 31;
    int side  = chain >> 1, dir = chain & 1;
    int j0    = blk * 16;
    int tid   = threadIdx.x;
    int lane  = tid & 31, warp = tid >> 5;
    const int* lens = side ? len2 : len1;
    const unsigned short* gi = g_gi[chain];
    unsigned short* enc = g_enc[side];

    for (int i = tid; i < 48 * 512; i += 256) {
        int rr = i >> 9, k = i & 511;
        int g = rr >> 4, u = rr & 15;
        Ws16[rr * HSTR + k] = f2b(whh[((size_t)dir * G3 + g * 512 + j0 + u) * 512 + k]);
    }

    int gb  = tid & 31;
    int u0  = tid >> 5;
    int u1  = u0 + 8;
    int lenb = lens[gb];
    float bhr0 = bhh[dir * G3 +        j0 + u0];
    float bhz0 = bhh[dir * G3 +  512 + j0 + u0];
    float bhn0 = bhh[dir * G3 + 1024 + j0 + u0];
    float bhr1 = bhh[dir * G3 +        j0 + u1];
    float bhz1 = bhh[dir * G3 +  512 + j0 + u1];
    float bhn1 = bhh[dir * G3 + 1024 + j0 + u1];

    // coalesced gi staging geometry: element e -> (gb = e/48, gate = (e%48)>>4, uu = e&15)
    int ge[6], gdst[6];
#pragma unroll
    for (int i = 0; i < 6; i++) {
        int e = tid + i * 256;
        int egb = e / 48, rem = e % 48;
        int gate = rem >> 4, uu = rem & 15;
        ge[i]   = (egb << 9) * G3 + gate * 512 + j0 + uu;   // + t*G3 at runtime
        gdst[i] = (gate * 16 + uu) * 33 + egb;
    }

    int kbase = warp << 6;
    unsigned tgt = 0;
    for (int t = 0; t < Lq; ++t) {
        int p = t & 1;
        const unsigned short* hsrc = g_h[chain][p];
        for (int i = tid; i < 2048; i += 256) {
            uint4 v = __ldcg((const uint4*)(hsrc + i * 8));
            int b = i >> 6, k = (i & 63) * 8;
            *(uint4*)(hT16 + b * HSTR + k) = v;
        }
        // coalesced gi load (32B sector per (gb,gate), fully used)
        {
            const unsigned short* gt = gi + (size_t)t * G3;
#pragma unroll
            for (int i = 0; i < 6; i++)
                gis[gdst[i]] = __ldg(gt + ge[i]);
        }
        __syncthreads();

        float acc[3][4][4];
#pragma unroll
        for (int mt = 0; mt < 3; mt++)
#pragma unroll
            for (int nt = 0; nt < 4; nt++)
#pragma unroll
                for (int r = 0; r < 4; r++) acc[mt][nt][r] = 0.f;

        const unsigned* Wsu = (const unsigned*)Ws16;
        const unsigned* hTu = (const unsigned*)hT16;
#pragma unroll
        for (int ks = 0; ks < 4; ks++) {
            int k0 = kbase + ks * 16;
            int kq = (k0 >> 1) + (lane & 3);
            unsigned a[3][4];
#pragma unroll
            for (int mt = 0; mt < 3; mt++) {
                int ao = (mt * 16 + (lane >> 2)) * 260 + kq;
                a[mt][0] = Wsu[ao];
                a[mt][1] = Wsu[ao + 8 * 260];
                a[mt][2] = Wsu[ao + 4];
                a[mt][3] = Wsu[ao + 8 * 260 + 4];
            }
            unsigned bfr[4][2];
#pragma unroll
            for (int nt = 0; nt < 4; nt++) {
                int bo = (nt * 8 + (lane >> 2)) * 260 + kq;
                bfr[nt][0] = hTu[bo];
                bfr[nt][1] = hTu[bo + 4];
            }
#pragma unroll
            for (int mt = 0; mt < 3; mt++)
#pragma unroll
                for (int nt = 0; nt < 4; nt++) {
                    asm volatile(
                        "mma.sync.aligned.m16n8k16.row.col.f32.bf16.bf16.f32 "
                        "{%0,%1,%2,%3}, {%4,%5,%6,%7}, {%8,%9}, {%0,%1,%2,%3};"
                        : "+f"(acc[mt][nt][0]), "+f"(acc[mt][nt][1]),
                          "+f"(acc[mt][nt][2]), "+f"(acc[mt][nt][3])
                        : "r"(a[mt][0]), "r"(a[mt][1]), "r"(a[mt][2]), "r"(a[mt][3]),
                          "r"(bfr[nt][0]), "r"(bfr[nt][1]));
                }
        }
        {
            float* pw = part + warp * (48 * 33);
            int crow = lane >> 2, ccol = 2 * (lane & 3);
#pragma unroll
            for (int mt = 0; mt < 3; mt++)
#pragma unroll
                for (int nt = 0; nt < 4; nt++) {
                    int r0 = mt * 16 + crow;
                    int c0 = nt * 8 + ccol;
                    pw[r0 * 33 + c0]           = acc[mt][nt][0];
                    pw[r0 * 33 + c0 + 1]       = acc[mt][nt][1];
                    pw[(r0 + 8) * 33 + c0]     = acc[mt][nt][2];
                    pw[(r0 + 8) * 33 + c0 + 1] = acc[mt][nt][3];
                }
        }
        __syncthreads();

        for (int i = tid; i < 1536; i += 256) {
            int rr = i >> 5, b = i & 31;
            float s = 0.f;
#pragma unroll
            for (int w = 0; w < 8; w++) s += part[w * (48 * 33) + rr * 33 + b];
            part[rr * 33 + b] = s;
        }
        __syncthreads();

        bool valid = t < lenb;
        int tout = dir ? (valid ? lenb - 1 - t : t) : t;
        size_t otok = (size_t)((gb << 9) | tout);
        unsigned short* hdst = g_h[chain][p ^ 1];

        unsigned short e0, e1;
        {
            float ir = b2f(gis[u0 * 33 + gb]);
            float iz = b2f(gis[(16 + u0) * 33 + gb]);
            float in = b2f(gis[(32 + u0) * 33 + gb]);
            unsigned short hpb = hT16[gb * HSTR + j0 + u0];
            float hprev = b2f(hpb);
            float hr = part[u0 * 33 + gb] + bhr0;
            float hz = part[(16 + u0) * 33 + gb] + bhz0;
            float hn = part[(32 + u0) * 33 + gb] + bhn0;
            float r  = 1.f / (1.f + expf(-(ir + hr)));
            float zz = 1.f / (1.f + expf(-(iz + hz)));
            float nn = tanhf(in + r * hn);
            float hnew = (1.f - zz) * nn + zz * hprev;
            unsigned short hb = f2b(hnew);
            hdst[gb * 512 + j0 + u0] = valid ? hb : hpb;
            e0 = valid ? hb : 0;
        }
        {
            float ir = b2f(gis[u1 * 33 + gb]);
            float iz = b2f(gis[(16 + u1) * 33 + gb]);
            float in = b2f(gis[(32 + u1) * 33 + gb]);
            unsigned short hpb = hT16[gb * HSTR + j0 + u1];
            float hprev = b2f(hpb);
            float hr = part[u1 * 33 + gb] + bhr1;
            float hz = part[(16 + u1) * 33 + gb] + bhz1;
            float hn = part[(32 + u1) * 33 + gb] + bhn1;
            float r  = 1.f / (1.f + expf(-(ir + hr)));
            float zz = 1.f / (1.f + expf(-(iz + hz)));
            float nn = tanhf(in + r * hn);
            float hnew = (1.f - zz) * nn + zz * hprev;
            unsigned short hb = f2b(hnew);
            hdst[gb * 512 + j0 + u1] = valid ? hb : hpb;
            e1 = valid ? hb : 0;
        }

        __threadfence();
        __syncthreads();
        tgt += 32;
        if (tid == 0) atomicAdd(&g_ctr[chain], 1u);
        enc[otok * 1024 + (dir << 9) + j0 + u0] = e0;
        enc[otok * 1024 + (dir << 9) + j0 + u1] = e1;
        if (tid == 0) {
            while (*(volatile unsigned*)&g_ctr[chain] < tgt) { }
        }
        __syncthreads();
    }
}

// ------------------------- row inverse-norms of enc (bf16 input) -------------------------
__global__ void k_norm() {
    const unsigned short* row = g_enc[blockIdx.y] + (size_t)blockIdx.x * 1024;
    int tid = threadIdx.x;
    uint4 v = ((const uint4*)row)[tid];
    float ss = 0.f;
    unsigned ws[4] = { v.x, v.y, v.z, v.w };
#pragma unroll
    for (int i = 0; i < 4; i++) {
        float a = b2f((unsigned short)(ws[i] & 0xffff));
        float b = b2f((unsigned short)(ws[i] >> 16));
        ss += a * a + b * b;
    }
    __shared__ float red[4];
    for (int o = 16; o; o >>= 1) ss += __shfl_down_sync(0xffffffffu, ss, o);
    if ((tid & 31) == 0) red[tid >> 5] = ss;
    __syncthreads();
    if (tid == 0) {
        float tot = red[0] + red[1] + red[2] + red[3];
        g_rn[blockIdx.y][blockIdx.x] = tot > 0.f ? rsqrtf(tot) : 0.f;
    }
}

// ------------------------- row / col max+argmax (first-index ties) -------------------------
__global__ void k_rowmax() {
    int row = blockIdx.x * 8 + (threadIdx.x >> 5);
    int l = threadIdx.x & 31;
    const float* s = g_sim + (size_t)row * Lq;
    float bv = -1e30f; int bi = 0;
    for (int j = l; j < Lq; j += 32) {
        float v = s[j];
        if (v > bv) { bv = v; bi = j; }
    }
    for (int o = 16; o; o >>= 1) {
        float ov = __shfl_down_sync(0xffffffffu, bv, o);
        int   oi = __shfl_down_sync(0xffffffffu, bi, o);
        if (ov > bv || (ov == bv && oi < bi)) { bv = ov; bi = oi; }
    }
    if (l == 0) {
        int i = row & 511;
        g_max1[row] = bv;
        g_rel1[row] = (float)(i - bi);
    }
}

__global__ void k_colmax() {
    int id = blockIdx.x * blockDim.x + threadIdx.x;
    int b = id >> 9, j = id & 511;
    const float* s = g_sim + ((size_t)b * Lq) * Lq + j;
    float bv = -1e30f; int bi = 0;
    for (int i = 0; i < Lq; ++i) {
        float v = s[(size_t)i * Lq];
        if (v > bv) { bv = v; bi = i; }
    }
    g_max2[id] = bv;
    g_rel2[id] = (float)(j - bi);
}

// ------------------------- conv branches + maxpool -------------------------
__global__ void k_head(const float* __restrict__ w2p, const float* __restrict__ w3p,
                       const float* __restrict__ w4p, const float* __restrict__ cb,
                       const float* __restrict__ bg, const float* __restrict__ bb,
                       const float* __restrict__ bm, const float* __restrict__ bvv)
{
    int b = blockIdx.x, br = blockIdx.y;
    __shared__ float x0[512], x1[512];
    const float* ms = br ? g_max2 : g_max1;
    const float* rl = br ? g_rel2 : g_rel1;
    for (int i = threadIdx.x; i < 512; i += 128) {
        x0[i] = ms[b * 512 + i];
        x1[i] = rl[b * 512 + i];
    }
    __syncthreads();
    int c = threadIdx.x;
    float* fout = g_feat + b * 768 + br * 384;
    const float* wp[3] = { w2p, w3p, w4p };
    const int kss[3] = { 2, 3, 4 };
    for (int ki = 0; ki < 3; ++ki) {
        int ks = kss[ki];
        float w0[4], w1[4];
        for (int kk = 0; kk < 4; kk++) {
            w0[kk] = kk < ks ? wp[ki][(c * 2 + 0) * ks + kk] : 0.f;
            w1[kk] = kk < ks ? wp[ki][(c * 2 + 1) * ks + kk] : 0.f;
        }
        float s  = bg[ki * 128 + c] / sqrtf(bvv[ki * 128 + c] + 1e-5f);
        float sh = bb[ki * 128 + c] - bm[ki * 128 + c] * s;
        float bias = cb[ki * 128 + c];
        float best = 0.f;
        for (int p = 0; p <= 512 - ks; ++p) {
            float acc = bias;
#pragma unroll
            for (int kk = 0; kk < 4; kk++)
                if (kk < ks) acc += w0[kk] * x0[p + kk] + w1[kk] * x1[p + kk];
            float y = fmaxf(acc * s + sh, 0.f);
            best = fmaxf(best, y);
        }
        fout[ki * 128 + c] = best;
    }
}

// ------------------------- FC + softmax -------------------------
__global__ void k_fc(const float* __restrict__ fcw, const float* __restrict__ fcb,
                     float* __restrict__ out)
{
    int id = threadIdx.x;
    int b = id >> 1, cls = id & 1;
    float acc = fcb[cls];
    const float* f = g_feat + b * 768;
    const float* wrow = fcw + cls * 768;
    for (int k = 0; k < 768; ++k) acc += f[k] * wrow[k];
    float other = __shfl_xor_sync(0xffffffffu, acc, 1);
    float m = fmaxf(acc, other);
    float e = expf(acc - m);
    float ssum = e + expf(other - m);
    out[id] = e / ssum;
}

// ------------------------- launch -------------------------
extern "C" void kernel_launch(void* const* d_in, const int* in_sizes, int n_in,
                              void* d_out, int out_size)
{
    const int* w1  = (const int*)d_in[0];
    const int* w2  = (const int*)d_in[1];
    const int* p1  = (const int*)d_in[2];
    const int* p2  = (const int*)d_in[3];
    const int* ln1 = (const int*)d_in[4];
    const int* ln2 = (const int*)d_in[5];
    const int* tb1 = (const int*)d_in[6];
    const int* te1 = (const int*)d_in[7];
    const int* tb2 = (const int*)d_in[8];
    const int* te2 = (const int*)d_in[9];
    const float* ew   = (const float*)d_in[10];
    const float* ep   = (const float*)d_in[11];
    const float* pe   = (const float*)d_in[12];
    const float* wih  = (const float*)d_in[13];
    const float* whh  = (const float*)d_in[14];
    const float* bih  = (const float*)d_in[15];
    const float* bhh  = (const float*)d_in[16];
    const float* cw0  = (const float*)d_in[17];
    const float* cw1  = (const float*)d_in[18];
    const float* cw2  = (const float*)d_in[19];
    const float* cb   = (const float*)d_in[20];
    const float* bg   = (const float*)d_in[21];
    const float* bb   = (const float*)d_in[22];
    const float* bm   = (const float*)d_in[23];
    const float* bv   = (const float*)d_in[24];
    const float* fcw  = (const float*)d_in[25];
    const float* fcb  = (const float*)d_in[26];
    float* out = (float*)d_out;

    cudaFuncSetAttribute(k_gemm16, cudaFuncAttributeMaxDynamicSharedMemorySize, G16_SMEM);
    cudaFuncSetAttribute(k_sim16, cudaFuncAttributeMaxDynamicSharedMemorySize, G16_SMEM);
    cudaFuncSetAttribute(k_gru, cudaFuncAttributeMaxDynamicSharedMemorySize, GRU_SMEM);

    k_init<<<512, 256>>>();
    k_cvtw<<<2 * G3 * DIN / 256, 256>>>(wih);
    k_embed<<<dim3(BL, 2), 128>>>(w1, w2, p1, p2, tb1, te1, tb2, te2, ew, ep, pe);
    k_gemm16<<<dim3(G3 / 128, BL / 128, 4), 256, G16_SMEM>>>(bih, ln1, ln2);
    k_gru<<<128, 256, GRU_SMEM>>>(whh, bhh, ln1, ln2);
    k_norm<<<dim3(BL, 2), 128>>>();
    k_sim16<<<dim3(Lq / 128, Lq / 128, Bq), 256, G16_SMEM>>>();
    k_rowmax<<<BL / 8, 256>>>();
    k_colmax<<<BL / 256, 256>>>();
    k_head<<<dim3(Bq, 2), 128>>>(cw0, cw1, cw2, cb, bg, bb, bm, bv);
    k_fc<<<1, 64>>>(fcw, fcb, out);
}